// round 11
// baseline (speedup 1.0000x reference)
#include <cuda_runtime.h>
#include <cuda_bf16.h>
#include <cstdint>

// Problem constants
#define N_TOK   262144
#define DIM     384
#define KCODES  512
#define BETA    0.25f

#define FP_TOK   64                     // tokens per fastpass block
#define FP_NBLK  (N_TOK / FP_TOK)       // 4096
#define RF_TOK   128                    // tokens per refine block
#define RF_NBLK  (N_TOK / RF_TOK)       // 2048
#define CODES_PC 64                     // codes per chunk
#define NCHUNK  (KCODES / CODES_PC)     // 8
#define TAU     0.06f                   // bf16 candidate margin
#define MAXCAND 16
#define ZROWB   784                     // padded bf16 smem row: 384*2 + 16 bytes

__device__ float g_esq[KCODES];
__device__ float g_part[RF_NBLK];
__device__ __nv_bfloat16 g_zbf[(size_t)N_TOK * DIM];
__device__ __nv_bfloat16 g_ebf[(size_t)KCODES * DIM];
__device__ int g_ccnt[N_TOK];
__device__ unsigned short g_cand[(size_t)N_TOK * MAXCAND];

// ---------------- PTX helpers (base sm_103 ISA only) ----------------
__device__ __forceinline__ uint32_t smem_u32(const void* p) {
    uint32_t a;
    asm("{ .reg .u64 t; cvta.to.shared.u64 t, %1; cvt.u32.u64 %0, t; }" : "=r"(a) : "l"(p));
    return a;
}

#define LDSM_X4(r0, r1, r2, r3, a) \
    asm volatile("ldmatrix.sync.aligned.m8n8.x4.shared.b16 {%0,%1,%2,%3}, [%4];" \
                 : "=r"(r0), "=r"(r1), "=r"(r2), "=r"(r3) : "r"(a))

#define MMA16816(d, a0, a1, a2, a3, b0, b1) \
    asm volatile("mma.sync.aligned.m16n8k16.row.col.f32.bf16.bf16.f32 " \
                 "{%0,%1,%2,%3}, {%4,%5,%6,%7}, {%8,%9}, {%0,%1,%2,%3};" \
                 : "+f"((d)[0]), "+f"((d)[1]), "+f"((d)[2]), "+f"((d)[3]) \
                 : "r"(a0), "r"(a1), "r"(a2), "r"(a3), "r"(b0), "r"(b1))

#define CP_ASYNC16(dst, src) \
    asm volatile("cp.async.cg.shared.global [%0], [%1], 16;" \
                 :: "r"((uint32_t)(dst)), "l"(src) : "memory")
#define CP_COMMIT() asm volatile("cp.async.commit_group;" ::: "memory")
#define CP_WAIT0()  asm volatile("cp.async.wait_group 0;" ::: "memory")

// ============================================================
// Exact-semantics primitives (DO NOT CHANGE — verified R6/R8/R9)
// ============================================================
__device__ float xla_rowsum_sq_192(const float* __restrict__ x) {
    float W[6];
    #pragma unroll
    for (int w = 0; w < 6; w++) {
        float P[32];
        #pragma unroll
        for (int t = 0; t < 32; t++) {
            int b = (w * 32 + t) * 2;
            float p0 = __fmul_rn(x[b], x[b]);
            float p1 = __fmul_rn(x[b + 1], x[b + 1]);
            P[t] = __fadd_rn(p0, p1);
        }
        #pragma unroll
        for (int off = 16; off >= 1; off >>= 1) {
            #pragma unroll
            for (int t = 0; t < 16; t++)
                if (t < off) P[t] = __fadd_rn(P[t], P[t + off]);
        }
        W[w] = P[0];
    }
    float l0 = __fadd_rn(__fadd_rn(W[0], W[4]), W[2]);
    float l1 = __fadd_rn(__fadd_rn(W[1], W[5]), W[3]);
    return __fadd_rn(l0, l1);
}

__device__ __forceinline__ float exact_score(const float* __restrict__ zr,
                                             const float* __restrict__ er,
                                             float Z32, float esq32) {
    float acc = 0.f;
    #pragma unroll 4
    for (int d = 0; d < DIM; d++)
        acc = __fmaf_rn(zr[d], er[d], acc);
    float v1 = __fadd_rn(Z32, __fmul_rn(-2.f, acc));
    return __fadd_rn(v1, esq32);
}

// ============================================================
// Kernel 1: e_sq[k] (verified)
// ============================================================
__global__ void vq_esq_kernel(const float* __restrict__ emb) {
    int k = blockIdx.x * blockDim.x + threadIdx.x;
    if (k < KCODES)
        g_esq[k] = xla_rowsum_sq_192(emb + (size_t)k * DIM);
}

// ============================================================
// Kernel 2: fp32 -> bf16 conversion + candidate-count reset (R9-verified)
// ============================================================
__global__ void vq_cvt_kernel(const float* __restrict__ z,
                              const float* __restrict__ emb) {
    size_t i = (size_t)blockIdx.x * blockDim.x + threadIdx.x;
    size_t stride = (size_t)gridDim.x * blockDim.x;
    const size_t nz = (size_t)N_TOK * DIM / 2;
    for (size_t p = i; p < nz; p += stride) {
        float2 v = ((const float2*)z)[p];
        ((__nv_bfloat162*)g_zbf)[p] = __float22bfloat162_rn(v);
    }
    const size_t ne = (size_t)KCODES * DIM / 2;
    for (size_t p = i; p < ne; p += stride) {
        float2 v = ((const float2*)emb)[p];
        ((__nv_bfloat162*)g_ebf)[p] = __float22bfloat162_rn(v);
    }
    for (size_t p = i; p < N_TOK; p += stride) g_ccnt[p] = 0;
}

// ============================================================
// Kernel 3: fast pass — 64 tokens/block, 8 warps, 2 CTAs/SM
// warps: tw = wid&3 -> token group (16 tokens), cg = wid>>2 -> code half (32)
// ============================================================
#define FP_ESQ   0                        // 2048
#define FP_Z     2048                     // 64*784 = 50176
#define FP_E     52224                    // 64*784 = 50176
#define FP_TOTAL 102400                   // 2 CTAs/SM (<= 228KB combined)

__global__ __launch_bounds__(256, 2)
void vq_fastpass_kernel() {
    extern __shared__ char smem[];
    const uint32_t smb = smem_u32(smem);
    const int tid = threadIdx.x;
    const int wid = tid >> 5;
    const int lane = tid & 31;
    const int tw = wid & 3;            // token group (16 tokens)
    const int cg = wid >> 2;           // code half (32 codes)
    const int tok0 = blockIdx.x * FP_TOK;

    float* s_esq = (float*)(smem + FP_ESQ);
    for (int i = tid; i < KCODES; i += 256) s_esq[i] = g_esq[i];

    // z tile: 64 rows x 784B, async
    #pragma unroll
    for (int it = 0; it < 12; it++) {
        int idx = tid + it * 256;          // 0..3071 (16B units)
        int row = idx / 48, c = idx % 48;
        CP_ASYNC16(smb + FP_Z + row * ZROWB + c * 16,
                   g_zbf + (size_t)(tok0 + row) * DIM + c * 8);
    }

    // ldmatrix lane addressing
    const int lr = lane & 7;
    const int g4 = lane >> 3;
    const uint32_t aAddr0 = smb + FP_Z
        + (uint32_t)((tw * 16 + (g4 & 1) * 8 + lr) * ZROWB + ((g4 >> 1) * 8) * 2);
    const uint32_t bAddr0 = smb + FP_E
        + (uint32_t)((cg * 32 + (g4 >> 1) * 8 + lr) * ZROWB + ((g4 & 1) * 8) * 2);

    const int g  = lane >> 2;
    const int cq = lane & 3;
    const int tokA = tok0 + tw * 16 + g;     // global token ids
    const int tokB = tokA + 8;

    float bv0 = 3.4e38f, bv1 = 3.4e38f;

    for (int ch = 0; ch < NCHUNK; ch++) {
        // load emb chunk ch (single buffer; 2 CTAs/SM hide the wait)
        const int cc0g = ch * CODES_PC;
        #pragma unroll
        for (int it = 0; it < 12; it++) {
            int idx = tid + it * 256;
            int row = idx / 48, c = idx % 48;
            CP_ASYNC16(smb + FP_E + row * ZROWB + c * 16,
                       g_ebf + (size_t)(cc0g + row) * DIM + c * 8);
        }
        CP_COMMIT();
        CP_WAIT0();
        __syncthreads();

        const int cc0 = cc0g + cg * 32;      // this warp's 32 codes

        float acc[4][4];
        #pragma unroll
        for (int nt = 0; nt < 4; nt++)
            #pragma unroll
            for (int v = 0; v < 4; v++) acc[nt][v] = 0.f;

        #pragma unroll 4
        for (int ks = 0; ks < DIM / 16; ks++) {
            uint32_t a0, a1, a2, a3;
            LDSM_X4(a0, a1, a2, a3, aAddr0 + ks * 32);
            #pragma unroll
            for (int i = 0; i < 2; i++) {
                uint32_t b0, b1, b2, b3;
                LDSM_X4(b0, b1, b2, b3, bAddr0 + i * (16 * ZROWB) + ks * 32);
                MMA16816(acc[2 * i],     a0, a1, a2, a3, b0, b1);
                MMA16816(acc[2 * i + 1], a0, a1, a2, a3, b2, b3);
            }
        }

        // per-chunk min across this token's quad (this warp's 32 codes)
        float m0 = 3.4e38f, m1 = 3.4e38f;
        #pragma unroll
        for (int nt = 0; nt < 4; nt++) {
            int colb = cc0 + nt * 8 + cq * 2;
            float s00 = __fmaf_rn(-2.f, acc[nt][0], s_esq[colb]);
            float s01 = __fmaf_rn(-2.f, acc[nt][1], s_esq[colb + 1]);
            float s10 = __fmaf_rn(-2.f, acc[nt][2], s_esq[colb]);
            float s11 = __fmaf_rn(-2.f, acc[nt][3], s_esq[colb + 1]);
            m0 = fminf(m0, fminf(s00, s01));
            m1 = fminf(m1, fminf(s10, s11));
        }
        m0 = fminf(m0, __shfl_xor_sync(0xffffffffu, m0, 1));
        m0 = fminf(m0, __shfl_xor_sync(0xffffffffu, m0, 2));
        m1 = fminf(m1, __shfl_xor_sync(0xffffffffu, m1, 1));
        m1 = fminf(m1, __shfl_xor_sync(0xffffffffu, m1, 2));
        bv0 = fminf(bv0, m0);
        bv1 = fminf(bv1, m1);
        const float lim0 = bv0 + TAU, lim1 = bv1 + TAU;

        // candidate collection vs running warp-local min (superset-safe)
        #pragma unroll
        for (int nt = 0; nt < 4; nt++) {
            int colb = cc0 + nt * 8 + cq * 2;
            #pragma unroll
            for (int v = 0; v < 4; v++) {
                int col = colb + (v & 1);
                float s = __fmaf_rn(-2.f, acc[nt][v], s_esq[col]);
                int tok = (v < 2) ? tokA : tokB;
                float lim = (v < 2) ? lim0 : lim1;
                if (s <= lim) {
                    int p = atomicAdd(&g_ccnt[tok], 1);
                    if (p < MAXCAND) g_cand[(size_t)tok * MAXCAND + p] = (unsigned short)col;
                }
            }
        }
        __syncthreads();   // all reads of emb buffer done before next chunk
    }
}

// ============================================================
// Kernel 4: refine + epilogue (exact R6 semantics — unchanged from R9)
// ============================================================
#define RF_ZROW  385                       // padded fp32 row (conflict-free LDS)
#define RF_Z     0                         // 128*385*4 = 197120
#define RF_ESQ   197120                    // 2048
#define RF_BESTI 199168                    // 512
#define RF_RED   199680                    // 1024
#define RF_TOTAL 200704

__global__ __launch_bounds__(256, 1)
void vq_refine_kernel(const float* __restrict__ z,
                      const float* __restrict__ emb,
                      float* __restrict__ out) {
    extern __shared__ char smem[];
    float* s_z = (float*)(smem + RF_Z);
    float* s_esq = (float*)(smem + RF_ESQ);
    int* s_besti = (int*)(smem + RF_BESTI);
    float* s_red = (float*)(smem + RF_RED);
    const int tid = threadIdx.x;
    const int tok0 = blockIdx.x * RF_TOK;

    for (int i = tid; i < KCODES; i += 256) s_esq[i] = g_esq[i];

    // stage z tile coalesced: 128 rows x 384 floats (padded rows of 385)
    #pragma unroll
    for (int it = 0; it < 48; it++) {
        int idx = tid + it * 256;          // 0..12287
        int row = idx / 96, c = idx % 96;
        float4 v = *(const float4*)(z + (size_t)(tok0 + row) * DIM + c * 4);
        float* dst = s_z + row * RF_ZROW + c * 4;
        dst[0] = v.x; dst[1] = v.y; dst[2] = v.z; dst[3] = v.w;
    }
    __syncthreads();

    // exact refine (verified semantics — values/order identical)
    if (tid < RF_TOK) {
        int token = tok0 + tid;
        const float* zr = s_z + tid * RF_ZROW;
        float Z32 = xla_rowsum_sq_192(zr);

        int cnt = g_ccnt[token];
        float sBest = 3.4e38f;
        int iBest = 0x7fffffff;
        if (cnt <= MAXCAND) {
            for (int ci = 0; ci < cnt; ci++) {
                int k = g_cand[(size_t)token * MAXCAND + ci];
                float s = exact_score(zr, emb + (size_t)k * DIM, Z32, s_esq[k]);
                if (s < sBest || (s == sBest && k < iBest)) { sBest = s; iBest = k; }
            }
        } else {
            for (int k = 0; k < KCODES; k++) {
                float s = exact_score(zr, emb + (size_t)k * DIM, Z32, s_esq[k]);
                if (s < sBest || (s == sBest && k < iBest)) { sBest = s; iBest = k; }
            }
        }
        s_besti[tid] = iBest;
    }
    __syncthreads();

    // epilogue: z_q_out = fl(z + fl(z_q - z)), idx, loss partial
    float lsum = 0.f;
    const int NF4 = RF_TOK * (DIM / 4);   // 12288
    for (int i = tid; i < NF4; i += 256) {
        int t  = i / (DIM / 4);
        int d4 = i % (DIM / 4);
        int token = tok0 + t;
        int idx = s_besti[t];
        float4 e = *(const float4*)(emb + (size_t)idx * DIM + d4 * 4);
        const float* zp = s_z + t * RF_ZROW + d4 * 4;
        float dx = __fsub_rn(e.x, zp[0]);
        float dy = __fsub_rn(e.y, zp[1]);
        float dz = __fsub_rn(e.z, zp[2]);
        float dw = __fsub_rn(e.w, zp[3]);
        lsum += dx * dx + dy * dy + dz * dz + dw * dw;
        float4 o;
        o.x = __fadd_rn(zp[0], dx);
        o.y = __fadd_rn(zp[1], dy);
        o.z = __fadd_rn(zp[2], dz);
        o.w = __fadd_rn(zp[3], dw);
        *(float4*)(out + (size_t)token * DIM + d4 * 4) = o;
    }
    if (tid < RF_TOK)
        out[(size_t)N_TOK * DIM + tok0 + tid] = (float)s_besti[tid];

    s_red[tid] = lsum;
    __syncthreads();
    #pragma unroll
    for (int s = 128; s > 0; s >>= 1) {
        if (tid < s) s_red[tid] += s_red[tid + s];
        __syncthreads();
    }
    if (tid == 0) g_part[blockIdx.x] = s_red[0];
}

// ============================================================
// Kernel 5: deterministic loss finalize
// ============================================================
__global__ void vq_finalize_kernel(float* __restrict__ out) {
    __shared__ float red[512];
    int tid = threadIdx.x;
    float s = 0.f;
    for (int i = tid; i < RF_NBLK; i += 512) s += g_part[i];
    red[tid] = s;
    __syncthreads();
    #pragma unroll
    for (int o = 256; o > 0; o >>= 1) {
        if (tid < o) red[tid] += red[tid + o];
        __syncthreads();
    }
    if (tid == 0) {
        float mean = red[0] / (float)((size_t)N_TOK * DIM);
        out[(size_t)N_TOK * DIM + N_TOK] = (1.0f + BETA) * mean;
    }
}

// ============================================================
extern "C" void kernel_launch(void* const* d_in, const int* in_sizes, int n_in,
                              void* d_out, int out_size) {
    const float* z   = (const float*)d_in[0];
    const float* emb = (const float*)d_in[1];
    float* out = (float*)d_out;

    cudaFuncSetAttribute(vq_fastpass_kernel,
                         cudaFuncAttributeMaxDynamicSharedMemorySize, FP_TOTAL);
    cudaFuncSetAttribute(vq_refine_kernel,
                         cudaFuncAttributeMaxDynamicSharedMemorySize, RF_TOTAL);

    vq_cvt_kernel<<<2048, 256>>>(z, emb);
    vq_esq_kernel<<<2, 256>>>(emb);
    vq_fastpass_kernel<<<FP_NBLK, 256, FP_TOTAL>>>();
    vq_refine_kernel<<<RF_NBLK, 256, RF_TOTAL>>>(z, emb, out);
    vq_finalize_kernel<<<1, 512>>>(out);
}

// round 12
// speedup vs baseline: 3.2004x; 3.2004x over previous
#include <cuda_runtime.h>
#include <cuda_bf16.h>
#include <cstdint>

// Problem constants
#define N_TOK   262144
#define DIM     384
#define KCODES  512
#define BETA    0.25f

#define TOK_PB  128                    // tokens per block
#define NBLOCKS (N_TOK / TOK_PB)       // 2048
#define CODES_PC 64                    // codes per chunk
#define NCHUNK  (KCODES / CODES_PC)    // 8
#define TAU     0.06f                  // bf16 candidate margin
#define MAXCAND 16
#define ZROWB   784                    // padded bf16 smem row: 384*2 + 16 bytes

__device__ float g_esq[KCODES];
__device__ float g_part[NBLOCKS];
__device__ __nv_bfloat16 g_zbf[(size_t)N_TOK * DIM];
__device__ __nv_bfloat16 g_ebf[(size_t)KCODES * DIM];
__device__ int g_ccnt[N_TOK];
__device__ unsigned short g_cand[(size_t)N_TOK * MAXCAND];

// ---------------- PTX helpers (base sm_103 ISA only) ----------------
__device__ __forceinline__ uint32_t smem_u32(const void* p) {
    uint32_t a;
    asm("{ .reg .u64 t; cvta.to.shared.u64 t, %1; cvt.u32.u64 %0, t; }" : "=r"(a) : "l"(p));
    return a;
}

#define LDSM_X4(r0, r1, r2, r3, a) \
    asm volatile("ldmatrix.sync.aligned.m8n8.x4.shared.b16 {%0,%1,%2,%3}, [%4];" \
                 : "=r"(r0), "=r"(r1), "=r"(r2), "=r"(r3) : "r"(a))

#define MMA16816(d, a0, a1, a2, a3, b0, b1) \
    asm volatile("mma.sync.aligned.m16n8k16.row.col.f32.bf16.bf16.f32 " \
                 "{%0,%1,%2,%3}, {%4,%5,%6,%7}, {%8,%9}, {%0,%1,%2,%3};" \
                 : "+f"((d)[0]), "+f"((d)[1]), "+f"((d)[2]), "+f"((d)[3]) \
                 : "r"(a0), "r"(a1), "r"(a2), "r"(a3), "r"(b0), "r"(b1))

#define CP_ASYNC16(dst, src) \
    asm volatile("cp.async.cg.shared.global [%0], [%1], 16;" \
                 :: "r"((uint32_t)(dst)), "l"(src) : "memory")
#define CP_COMMIT() asm volatile("cp.async.commit_group;" ::: "memory")
#define CP_WAIT1()  asm volatile("cp.async.wait_group 1;" ::: "memory")
#define CP_WAIT0()  asm volatile("cp.async.wait_group 0;" ::: "memory")

// ============================================================
// Exact-semantics primitives (DO NOT CHANGE — verified R6/R8/R9)
// ============================================================
__device__ float xla_rowsum_sq_192(const float* __restrict__ x) {
    float W[6];
    #pragma unroll
    for (int w = 0; w < 6; w++) {
        float P[32];
        #pragma unroll
        for (int t = 0; t < 32; t++) {
            int b = (w * 32 + t) * 2;
            float p0 = __fmul_rn(x[b], x[b]);
            float p1 = __fmul_rn(x[b + 1], x[b + 1]);
            P[t] = __fadd_rn(p0, p1);
        }
        #pragma unroll
        for (int off = 16; off >= 1; off >>= 1) {
            #pragma unroll
            for (int t = 0; t < 16; t++)
                if (t < off) P[t] = __fadd_rn(P[t], P[t + off]);
        }
        W[w] = P[0];
    }
    float l0 = __fadd_rn(__fadd_rn(W[0], W[4]), W[2]);
    float l1 = __fadd_rn(__fadd_rn(W[1], W[5]), W[3]);
    return __fadd_rn(l0, l1);
}

__device__ __forceinline__ float exact_score(const float* __restrict__ zr,
                                             const float* __restrict__ er,
                                             float Z32, float esq32) {
    float acc = 0.f;
    #pragma unroll 4
    for (int d = 0; d < DIM; d++)
        acc = __fmaf_rn(zr[d], er[d], acc);
    float v1 = __fadd_rn(Z32, __fmul_rn(-2.f, acc));
    return __fadd_rn(v1, esq32);
}

// ============================================================
// Kernel 1: e_sq[k] (verified)
// ============================================================
__global__ void vq_esq_kernel(const float* __restrict__ emb) {
    int k = blockIdx.x * blockDim.x + threadIdx.x;
    if (k < KCODES)
        g_esq[k] = xla_rowsum_sq_192(emb + (size_t)k * DIM);
}

// ============================================================
// Kernel 2: fp32 -> bf16 conversion + candidate-count reset (verified)
// ============================================================
__global__ void vq_cvt_kernel(const float* __restrict__ z,
                              const float* __restrict__ emb) {
    size_t i = (size_t)blockIdx.x * blockDim.x + threadIdx.x;
    size_t stride = (size_t)gridDim.x * blockDim.x;
    const size_t nz = (size_t)N_TOK * DIM / 2;
    for (size_t p = i; p < nz; p += stride) {
        float2 v = ((const float2*)z)[p];
        ((__nv_bfloat162*)g_zbf)[p] = __float22bfloat162_rn(v);
    }
    const size_t ne = (size_t)KCODES * DIM / 2;
    for (size_t p = i; p < ne; p += stride) {
        float2 v = ((const float2*)emb)[p];
        ((__nv_bfloat162*)g_ebf)[p] = __float22bfloat162_rn(v);
    }
    for (size_t p = i; p < N_TOK; p += stride) g_ccnt[p] = 0;
}

// ============================================================
// Kernel 3: fast pass — R9 structure (256 thr, 8 warps, 1 CTA/SM,
// double-buffered emb) + register-level software pipelining of
// ldmatrix fragments (next k-step loads issued before current MMAs)
// ============================================================
#define FP_ESQ   0                        // 2048
#define FP_Z     2048                     // 128*784 = 100352
#define FP_E0    102400                   // 64*784  = 50176
#define FP_E1    152576                   // 50176
#define FP_TOTAL 202752

__global__ __launch_bounds__(256, 1)
void vq_fastpass_kernel() {
    extern __shared__ char smem[];
    const uint32_t smb = smem_u32(smem);
    const int tid = threadIdx.x;
    const int w   = tid >> 5;
    const int lane = tid & 31;
    const int tok0 = blockIdx.x * TOK_PB;

    float* s_esq = (float*)(smem + FP_ESQ);
    for (int i = tid; i < KCODES; i += 256) s_esq[i] = g_esq[i];

    // z tile (async) + first emb chunk (async), one group
    #pragma unroll
    for (int it = 0; it < 24; it++) {
        int idx = tid + it * 256;
        int row = idx / 48, c = idx % 48;
        CP_ASYNC16(smb + FP_Z + row * ZROWB + c * 16,
                   g_zbf + (size_t)(tok0 + row) * DIM + c * 8);
    }
    #pragma unroll
    for (int it = 0; it < 12; it++) {
        int idx = tid + it * 256;
        int row = idx / 48, c = idx % 48;
        CP_ASYNC16(smb + FP_E0 + row * ZROWB + c * 16,
                   g_ebf + (size_t)row * DIM + c * 8);
    }
    CP_COMMIT();

    // ldmatrix lane addressing
    const int lr = lane & 7;
    const int g4 = lane >> 3;
    const uint32_t aAddr0 = smb + FP_Z
        + (uint32_t)((w * 16 + (g4 & 1) * 8 + lr) * ZROWB + ((g4 >> 1) * 8) * 2);
    const uint32_t bOff = (uint32_t)(((g4 >> 1) * 8 + lr) * ZROWB + ((g4 & 1) * 8) * 2);
    const uint32_t bBase[2] = { smb + FP_E0 + bOff, smb + FP_E1 + bOff };

    const int g  = lane >> 2;
    const int cq = lane & 3;
    const int tokA = tok0 + w * 16 + g;     // global token ids
    const int tokB = tokA + 8;

    float bv0 = 3.4e38f, bv1 = 3.4e38f;

    for (int ch = 0; ch < NCHUNK; ch++) {
        if (ch + 1 < NCHUNK) {
            const int cc1 = (ch + 1) * CODES_PC;
            const uint32_t ebuf = (ch + 1) & 1 ? (smb + FP_E1) : (smb + FP_E0);
            #pragma unroll
            for (int it = 0; it < 12; it++) {
                int idx = tid + it * 256;
                int row = idx / 48, c = idx % 48;
                CP_ASYNC16(ebuf + row * ZROWB + c * 16,
                           g_ebf + (size_t)(cc1 + row) * DIM + c * 8);
            }
            CP_COMMIT();
            CP_WAIT1();
        } else {
            CP_WAIT0();
        }
        __syncthreads();

        const int cc0 = ch * CODES_PC;
        const uint32_t bAddr0 = bBase[ch & 1];

        float acc[8][4];
        #pragma unroll
        for (int nt = 0; nt < 8; nt++)
            #pragma unroll
            for (int v = 0; v < 4; v++) acc[nt][v] = 0.f;

        // ---- software-pipelined k-loop: frags double-buffered in regs ----
        uint32_t afr[2][4], bfr[2][16];
        LDSM_X4(afr[0][0], afr[0][1], afr[0][2], afr[0][3], aAddr0);
        #pragma unroll
        for (int i = 0; i < 4; i++)
            LDSM_X4(bfr[0][4 * i], bfr[0][4 * i + 1],
                    bfr[0][4 * i + 2], bfr[0][4 * i + 3],
                    bAddr0 + i * (16 * ZROWB));

        #pragma unroll
        for (int ks = 0; ks < DIM / 16; ks++) {
            const int cur = ks & 1, nxt = cur ^ 1;
            if (ks + 1 < DIM / 16) {
                LDSM_X4(afr[nxt][0], afr[nxt][1], afr[nxt][2], afr[nxt][3],
                        aAddr0 + (ks + 1) * 32);
                #pragma unroll
                for (int i = 0; i < 4; i++)
                    LDSM_X4(bfr[nxt][4 * i], bfr[nxt][4 * i + 1],
                            bfr[nxt][4 * i + 2], bfr[nxt][4 * i + 3],
                            bAddr0 + i * (16 * ZROWB) + (ks + 1) * 32);
            }
            #pragma unroll
            for (int i = 0; i < 4; i++) {
                MMA16816(acc[2 * i],     afr[cur][0], afr[cur][1], afr[cur][2], afr[cur][3],
                         bfr[cur][4 * i], bfr[cur][4 * i + 1]);
                MMA16816(acc[2 * i + 1], afr[cur][0], afr[cur][1], afr[cur][2], afr[cur][3],
                         bfr[cur][4 * i + 2], bfr[cur][4 * i + 3]);
            }
        }

        // per-chunk min across this token's quad
        float m0 = 3.4e38f, m1 = 3.4e38f;
        #pragma unroll
        for (int nt = 0; nt < 8; nt++) {
            int colb = cc0 + nt * 8 + cq * 2;
            float s00 = __fmaf_rn(-2.f, acc[nt][0], s_esq[colb]);
            float s01 = __fmaf_rn(-2.f, acc[nt][1], s_esq[colb + 1]);
            float s10 = __fmaf_rn(-2.f, acc[nt][2], s_esq[colb]);
            float s11 = __fmaf_rn(-2.f, acc[nt][3], s_esq[colb + 1]);
            m0 = fminf(m0, fminf(s00, s01));
            m1 = fminf(m1, fminf(s10, s11));
        }
        m0 = fminf(m0, __shfl_xor_sync(0xffffffffu, m0, 1));
        m0 = fminf(m0, __shfl_xor_sync(0xffffffffu, m0, 2));
        m1 = fminf(m1, __shfl_xor_sync(0xffffffffu, m1, 1));
        m1 = fminf(m1, __shfl_xor_sync(0xffffffffu, m1, 2));
        bv0 = fminf(bv0, m0);
        bv1 = fminf(bv1, m1);
        const float lim0 = bv0 + TAU, lim1 = bv1 + TAU;

        // candidate collection vs running min (superset-safe)
        #pragma unroll
        for (int nt = 0; nt < 8; nt++) {
            int colb = cc0 + nt * 8 + cq * 2;
            #pragma unroll
            for (int v = 0; v < 4; v++) {
                int col = colb + (v & 1);
                float s = __fmaf_rn(-2.f, acc[nt][v], s_esq[col]);
                int tok = (v < 2) ? tokA : tokB;
                float lim = (v < 2) ? lim0 : lim1;
                if (s <= lim) {
                    int p = atomicAdd(&g_ccnt[tok], 1);
                    if (p < MAXCAND) g_cand[(size_t)tok * MAXCAND + p] = (unsigned short)col;
                }
            }
        }
        __syncthreads();   // all reads of current emb buffer done before reuse
    }
}

// ============================================================
// Kernel 4: refine + epilogue (exact R6 semantics — unchanged from R9)
// ============================================================
#define RF_ZROW  385                       // padded fp32 row (conflict-free LDS)
#define RF_Z     0                         // 128*385*4 = 197120
#define RF_ESQ   197120                    // 2048
#define RF_BESTI 199168                    // 512
#define RF_RED   199680                    // 1024
#define RF_TOTAL 200704

__global__ __launch_bounds__(256, 1)
void vq_refine_kernel(const float* __restrict__ z,
                      const float* __restrict__ emb,
                      float* __restrict__ out) {
    extern __shared__ char smem[];
    float* s_z = (float*)(smem + RF_Z);
    float* s_esq = (float*)(smem + RF_ESQ);
    int* s_besti = (int*)(smem + RF_BESTI);
    float* s_red = (float*)(smem + RF_RED);
    const int tid = threadIdx.x;
    const int tok0 = blockIdx.x * TOK_PB;

    for (int i = tid; i < KCODES; i += 256) s_esq[i] = g_esq[i];

    // stage z tile coalesced: 128 rows x 384 floats (padded rows of 385)
    #pragma unroll
    for (int it = 0; it < 48; it++) {
        int idx = tid + it * 256;          // 0..12287
        int row = idx / 96, c = idx % 96;
        float4 v = *(const float4*)(z + (size_t)(tok0 + row) * DIM + c * 4);
        float* dst = s_z + row * RF_ZROW + c * 4;
        dst[0] = v.x; dst[1] = v.y; dst[2] = v.z; dst[3] = v.w;
    }
    __syncthreads();

    // exact refine (verified semantics — values/order identical)
    if (tid < TOK_PB) {
        int token = tok0 + tid;
        const float* zr = s_z + tid * RF_ZROW;
        float Z32 = xla_rowsum_sq_192(zr);

        int cnt = g_ccnt[token];
        float sBest = 3.4e38f;
        int iBest = 0x7fffffff;
        if (cnt <= MAXCAND) {
            for (int ci = 0; ci < cnt; ci++) {
                int k = g_cand[(size_t)token * MAXCAND + ci];
                float s = exact_score(zr, emb + (size_t)k * DIM, Z32, s_esq[k]);
                if (s < sBest || (s == sBest && k < iBest)) { sBest = s; iBest = k; }
            }
        } else {
            for (int k = 0; k < KCODES; k++) {
                float s = exact_score(zr, emb + (size_t)k * DIM, Z32, s_esq[k]);
                if (s < sBest || (s == sBest && k < iBest)) { sBest = s; iBest = k; }
            }
        }
        s_besti[tid] = iBest;
    }
    __syncthreads();

    // epilogue: z_q_out = fl(z + fl(z_q - z)), idx, loss partial
    float lsum = 0.f;
    const int NF4 = TOK_PB * (DIM / 4);   // 12288
    for (int i = tid; i < NF4; i += 256) {
        int t  = i / (DIM / 4);
        int d4 = i % (DIM / 4);
        int token = tok0 + t;
        int idx = s_besti[t];
        float4 e = *(const float4*)(emb + (size_t)idx * DIM + d4 * 4);
        const float* zp = s_z + t * RF_ZROW + d4 * 4;
        float dx = __fsub_rn(e.x, zp[0]);
        float dy = __fsub_rn(e.y, zp[1]);
        float dz = __fsub_rn(e.z, zp[2]);
        float dw = __fsub_rn(e.w, zp[3]);
        lsum += dx * dx + dy * dy + dz * dz + dw * dw;
        float4 o;
        o.x = __fadd_rn(zp[0], dx);
        o.y = __fadd_rn(zp[1], dy);
        o.z = __fadd_rn(zp[2], dz);
        o.w = __fadd_rn(zp[3], dw);
        *(float4*)(out + (size_t)token * DIM + d4 * 4) = o;
    }
    if (tid < TOK_PB)
        out[(size_t)N_TOK * DIM + tok0 + tid] = (float)s_besti[tid];

    s_red[tid] = lsum;
    __syncthreads();
    #pragma unroll
    for (int s = 128; s > 0; s >>= 1) {
        if (tid < s) s_red[tid] += s_red[tid + s];
        __syncthreads();
    }
    if (tid == 0) g_part[blockIdx.x] = s_red[0];
}

// ============================================================
// Kernel 5: deterministic loss finalize
// ============================================================
__global__ void vq_finalize_kernel(float* __restrict__ out) {
    __shared__ float red[512];
    int tid = threadIdx.x;
    float s = 0.f;
    for (int i = tid; i < NBLOCKS; i += 512) s += g_part[i];
    red[tid] = s;
    __syncthreads();
    #pragma unroll
    for (int o = 256; o > 0; o >>= 1) {
        if (tid < o) red[tid] += red[tid + o];
        __syncthreads();
    }
    if (tid == 0) {
        float mean = red[0] / (float)((size_t)N_TOK * DIM);
        out[(size_t)N_TOK * DIM + N_TOK] = (1.0f + BETA) * mean;
    }
}

// ============================================================
extern "C" void kernel_launch(void* const* d_in, const int* in_sizes, int n_in,
                              void* d_out, int out_size) {
    const float* z   = (const float*)d_in[0];
    const float* emb = (const float*)d_in[1];
    float* out = (float*)d_out;

    cudaFuncSetAttribute(vq_fastpass_kernel,
                         cudaFuncAttributeMaxDynamicSharedMemorySize, FP_TOTAL);
    cudaFuncSetAttribute(vq_refine_kernel,
                         cudaFuncAttributeMaxDynamicSharedMemorySize, RF_TOTAL);

    vq_cvt_kernel<<<2048, 256>>>(z, emb);
    vq_esq_kernel<<<2, 256>>>(emb);
    vq_fastpass_kernel<<<NBLOCKS, 256, FP_TOTAL>>>();
    vq_refine_kernel<<<NBLOCKS, 256, RF_TOTAL>>>(z, emb, out);
    vq_finalize_kernel<<<1, 512>>>(out);
}

// round 13
// speedup vs baseline: 5.1860x; 1.6204x over previous
#include <cuda_runtime.h>
#include <cuda_bf16.h>
#include <cstdint>

// Problem constants
#define N_TOK   262144
#define DIM     384
#define KCODES  512
#define BETA    0.25f

#define TOK_PB  128                    // tokens per block
#define NBLOCKS (N_TOK / TOK_PB)       // 2048
#define CODES_PC 64                    // codes per chunk
#define NCHUNK  (KCODES / CODES_PC)    // 8
#define TAU     0.06f                  // bf16 candidate margin
#define MAXCAND 16
#define ZROWB   784                    // padded bf16 smem row: 384*2 + 16 bytes

__device__ float g_esq[KCODES];
__device__ float g_part[NBLOCKS];
__device__ __nv_bfloat16 g_zbf[(size_t)N_TOK * DIM];
__device__ __nv_bfloat16 g_ebf[(size_t)KCODES * DIM];
__device__ int g_ccnt[N_TOK];
__device__ unsigned short g_cand[(size_t)N_TOK * MAXCAND];

// ---------------- PTX helpers (base sm_103 ISA only) ----------------
__device__ __forceinline__ uint32_t smem_u32(const void* p) {
    uint32_t a;
    asm("{ .reg .u64 t; cvta.to.shared.u64 t, %1; cvt.u32.u64 %0, t; }" : "=r"(a) : "l"(p));
    return a;
}

#define LDSM_X4(r0, r1, r2, r3, a) \
    asm volatile("ldmatrix.sync.aligned.m8n8.x4.shared.b16 {%0,%1,%2,%3}, [%4];" \
                 : "=r"(r0), "=r"(r1), "=r"(r2), "=r"(r3) : "r"(a))

#define MMA16816(d, a0, a1, a2, a3, b0, b1) \
    asm volatile("mma.sync.aligned.m16n8k16.row.col.f32.bf16.bf16.f32 " \
                 "{%0,%1,%2,%3}, {%4,%5,%6,%7}, {%8,%9}, {%0,%1,%2,%3};" \
                 : "+f"((d)[0]), "+f"((d)[1]), "+f"((d)[2]), "+f"((d)[3]) \
                 : "r"(a0), "r"(a1), "r"(a2), "r"(a3), "r"(b0), "r"(b1))

#define CP_ASYNC16(dst, src) \
    asm volatile("cp.async.cg.shared.global [%0], [%1], 16;" \
                 :: "r"((uint32_t)(dst)), "l"(src) : "memory")
#define CP_COMMIT() asm volatile("cp.async.commit_group;" ::: "memory")
#define CP_WAIT1()  asm volatile("cp.async.wait_group 1;" ::: "memory")
#define CP_WAIT0()  asm volatile("cp.async.wait_group 0;" ::: "memory")

// ============================================================
// Exact-semantics primitives (DO NOT CHANGE the op sequence —
// verified R6/R8/R9/R12)
// ============================================================
__device__ float xla_rowsum_sq_192(const float* __restrict__ x) {
    float W[6];
    #pragma unroll
    for (int w = 0; w < 6; w++) {
        float P[32];
        #pragma unroll
        for (int t = 0; t < 32; t++) {
            int b = (w * 32 + t) * 2;
            float p0 = __fmul_rn(x[b], x[b]);
            float p1 = __fmul_rn(x[b + 1], x[b + 1]);
            P[t] = __fadd_rn(p0, p1);
        }
        #pragma unroll
        for (int off = 16; off >= 1; off >>= 1) {
            #pragma unroll
            for (int t = 0; t < 16; t++)
                if (t < off) P[t] = __fadd_rn(P[t], P[t + off]);
        }
        W[w] = P[0];
    }
    float l0 = __fadd_rn(__fadd_rn(W[0], W[4]), W[2]);
    float l1 = __fadd_rn(__fadd_rn(W[1], W[5]), W[3]);
    return __fadd_rn(l0, l1);
}

// Same __fmaf_rn sequence as the verified scalar version (d ascending),
// but er fetched via float4 (LDG.128): 4x fewer L1tex wavefronts.
__device__ __forceinline__ float exact_score(const float* __restrict__ zr,
                                             const float* __restrict__ er,
                                             float Z32, float esq32) {
    float acc = 0.f;
    const float4* er4 = (const float4*)er;
    #pragma unroll 4
    for (int d4 = 0; d4 < DIM / 4; d4++) {
        float4 e = er4[d4];
        acc = __fmaf_rn(zr[4 * d4 + 0], e.x, acc);
        acc = __fmaf_rn(zr[4 * d4 + 1], e.y, acc);
        acc = __fmaf_rn(zr[4 * d4 + 2], e.z, acc);
        acc = __fmaf_rn(zr[4 * d4 + 3], e.w, acc);
    }
    float v1 = __fadd_rn(Z32, __fmul_rn(-2.f, acc));
    return __fadd_rn(v1, esq32);
}

// ============================================================
// Kernel A: z fp32 -> bf16 + candidate-count reset
// ============================================================
__global__ void vq_cvt_z_kernel(const float* __restrict__ z) {
    size_t i = (size_t)blockIdx.x * blockDim.x + threadIdx.x;
    size_t stride = (size_t)gridDim.x * blockDim.x;
    const size_t nz = (size_t)N_TOK * DIM / 2;
    for (size_t p = i; p < nz; p += stride) {
        float2 v = ((const float2*)z)[p];
        ((__nv_bfloat162*)g_zbf)[p] = __float22bfloat162_rn(v);
    }
    for (size_t p = i; p < N_TOK; p += stride) g_ccnt[p] = 0;
}

// ============================================================
// Kernel B: emb fp32 -> bf16
// ============================================================
__global__ void vq_cvt_e_kernel(const float* __restrict__ emb) {
    size_t i = (size_t)blockIdx.x * blockDim.x + threadIdx.x;
    size_t stride = (size_t)gridDim.x * blockDim.x;
    const size_t ne = (size_t)KCODES * DIM / 2;
    for (size_t p = i; p < ne; p += stride) {
        float2 v = ((const float2*)emb)[p];
        ((__nv_bfloat162*)g_ebf)[p] = __float22bfloat162_rn(v);
    }
}

// ============================================================
// Kernel C: e_sq[k] (verified)
// ============================================================
__global__ void vq_esq_kernel(const float* __restrict__ emb) {
    int k = blockIdx.x * blockDim.x + threadIdx.x;
    if (k < KCODES)
        g_esq[k] = xla_rowsum_sq_192(emb + (size_t)k * DIM);
}

// ============================================================
// Kernel D (launch idx 3 -> ncu capture): fast pass — R12 verified
// ============================================================
#define FP_ESQ   0                        // 2048
#define FP_Z     2048                     // 128*784 = 100352
#define FP_E0    102400                   // 64*784  = 50176
#define FP_E1    152576                   // 50176
#define FP_TOTAL 202752

__global__ __launch_bounds__(256, 1)
void vq_fastpass_kernel() {
    extern __shared__ char smem[];
    const uint32_t smb = smem_u32(smem);
    const int tid = threadIdx.x;
    const int w   = tid >> 5;
    const int lane = tid & 31;
    const int tok0 = blockIdx.x * TOK_PB;

    float* s_esq = (float*)(smem + FP_ESQ);
    for (int i = tid; i < KCODES; i += 256) s_esq[i] = g_esq[i];

    #pragma unroll
    for (int it = 0; it < 24; it++) {
        int idx = tid + it * 256;
        int row = idx / 48, c = idx % 48;
        CP_ASYNC16(smb + FP_Z + row * ZROWB + c * 16,
                   g_zbf + (size_t)(tok0 + row) * DIM + c * 8);
    }
    #pragma unroll
    for (int it = 0; it < 12; it++) {
        int idx = tid + it * 256;
        int row = idx / 48, c = idx % 48;
        CP_ASYNC16(smb + FP_E0 + row * ZROWB + c * 16,
                   g_ebf + (size_t)row * DIM + c * 8);
    }
    CP_COMMIT();

    const int lr = lane & 7;
    const int g4 = lane >> 3;
    const uint32_t aAddr0 = smb + FP_Z
        + (uint32_t)((w * 16 + (g4 & 1) * 8 + lr) * ZROWB + ((g4 >> 1) * 8) * 2);
    const uint32_t bOff = (uint32_t)(((g4 >> 1) * 8 + lr) * ZROWB + ((g4 & 1) * 8) * 2);
    const uint32_t bBase[2] = { smb + FP_E0 + bOff, smb + FP_E1 + bOff };

    const int g  = lane >> 2;
    const int cq = lane & 3;
    const int tokA = tok0 + w * 16 + g;
    const int tokB = tokA + 8;

    float bv0 = 3.4e38f, bv1 = 3.4e38f;

    for (int ch = 0; ch < NCHUNK; ch++) {
        if (ch + 1 < NCHUNK) {
            const int cc1 = (ch + 1) * CODES_PC;
            const uint32_t ebuf = (ch + 1) & 1 ? (smb + FP_E1) : (smb + FP_E0);
            #pragma unroll
            for (int it = 0; it < 12; it++) {
                int idx = tid + it * 256;
                int row = idx / 48, c = idx % 48;
                CP_ASYNC16(ebuf + row * ZROWB + c * 16,
                           g_ebf + (size_t)(cc1 + row) * DIM + c * 8);
            }
            CP_COMMIT();
            CP_WAIT1();
        } else {
            CP_WAIT0();
        }
        __syncthreads();

        const int cc0 = ch * CODES_PC;
        const uint32_t bAddr0 = bBase[ch & 1];

        float acc[8][4];
        #pragma unroll
        for (int nt = 0; nt < 8; nt++)
            #pragma unroll
            for (int v = 0; v < 4; v++) acc[nt][v] = 0.f;

        uint32_t afr[2][4], bfr[2][16];
        LDSM_X4(afr[0][0], afr[0][1], afr[0][2], afr[0][3], aAddr0);
        #pragma unroll
        for (int i = 0; i < 4; i++)
            LDSM_X4(bfr[0][4 * i], bfr[0][4 * i + 1],
                    bfr[0][4 * i + 2], bfr[0][4 * i + 3],
                    bAddr0 + i * (16 * ZROWB));

        #pragma unroll
        for (int ks = 0; ks < DIM / 16; ks++) {
            const int cur = ks & 1, nxt = cur ^ 1;
            if (ks + 1 < DIM / 16) {
                LDSM_X4(afr[nxt][0], afr[nxt][1], afr[nxt][2], afr[nxt][3],
                        aAddr0 + (ks + 1) * 32);
                #pragma unroll
                for (int i = 0; i < 4; i++)
                    LDSM_X4(bfr[nxt][4 * i], bfr[nxt][4 * i + 1],
                            bfr[nxt][4 * i + 2], bfr[nxt][4 * i + 3],
                            bAddr0 + i * (16 * ZROWB) + (ks + 1) * 32);
            }
            #pragma unroll
            for (int i = 0; i < 4; i++) {
                MMA16816(acc[2 * i],     afr[cur][0], afr[cur][1], afr[cur][2], afr[cur][3],
                         bfr[cur][4 * i], bfr[cur][4 * i + 1]);
                MMA16816(acc[2 * i + 1], afr[cur][0], afr[cur][1], afr[cur][2], afr[cur][3],
                         bfr[cur][4 * i + 2], bfr[cur][4 * i + 3]);
            }
        }

        float m0 = 3.4e38f, m1 = 3.4e38f;
        #pragma unroll
        for (int nt = 0; nt < 8; nt++) {
            int colb = cc0 + nt * 8 + cq * 2;
            float s00 = __fmaf_rn(-2.f, acc[nt][0], s_esq[colb]);
            float s01 = __fmaf_rn(-2.f, acc[nt][1], s_esq[colb + 1]);
            float s10 = __fmaf_rn(-2.f, acc[nt][2], s_esq[colb]);
            float s11 = __fmaf_rn(-2.f, acc[nt][3], s_esq[colb + 1]);
            m0 = fminf(m0, fminf(s00, s01));
            m1 = fminf(m1, fminf(s10, s11));
        }
        m0 = fminf(m0, __shfl_xor_sync(0xffffffffu, m0, 1));
        m0 = fminf(m0, __shfl_xor_sync(0xffffffffu, m0, 2));
        m1 = fminf(m1, __shfl_xor_sync(0xffffffffu, m1, 1));
        m1 = fminf(m1, __shfl_xor_sync(0xffffffffu, m1, 2));
        bv0 = fminf(bv0, m0);
        bv1 = fminf(bv1, m1);
        const float lim0 = bv0 + TAU, lim1 = bv1 + TAU;

        #pragma unroll
        for (int nt = 0; nt < 8; nt++) {
            int colb = cc0 + nt * 8 + cq * 2;
            #pragma unroll
            for (int v = 0; v < 4; v++) {
                int col = colb + (v & 1);
                float s = __fmaf_rn(-2.f, acc[nt][v], s_esq[col]);
                int tok = (v < 2) ? tokA : tokB;
                float lim = (v < 2) ? lim0 : lim1;
                if (s <= lim) {
                    int p = atomicAdd(&g_ccnt[tok], 1);
                    if (p < MAXCAND) g_cand[(size_t)tok * MAXCAND + p] = (unsigned short)col;
                }
            }
        }
        __syncthreads();
    }
}

// ============================================================
// Kernel E: refine + epilogue (verified semantics; er via float4)
// ============================================================
#define RF_ZROW  385
#define RF_Z     0                         // 128*385*4 = 197120
#define RF_ESQ   197120                    // 2048
#define RF_BESTI 199168                    // 512
#define RF_RED   199680                    // 1024
#define RF_TOTAL 200704

__global__ __launch_bounds__(256, 1)
void vq_refine_kernel(const float* __restrict__ z,
                      const float* __restrict__ emb,
                      float* __restrict__ out) {
    extern __shared__ char smem[];
    float* s_z = (float*)(smem + RF_Z);
    float* s_esq = (float*)(smem + RF_ESQ);
    int* s_besti = (int*)(smem + RF_BESTI);
    float* s_red = (float*)(smem + RF_RED);
    const int tid = threadIdx.x;
    const int tok0 = blockIdx.x * TOK_PB;

    for (int i = tid; i < KCODES; i += 256) s_esq[i] = g_esq[i];

    #pragma unroll
    for (int it = 0; it < 48; it++) {
        int idx = tid + it * 256;
        int row = idx / 96, c = idx % 96;
        float4 v = *(const float4*)(z + (size_t)(tok0 + row) * DIM + c * 4);
        float* dst = s_z + row * RF_ZROW + c * 4;
        dst[0] = v.x; dst[1] = v.y; dst[2] = v.z; dst[3] = v.w;
    }
    __syncthreads();

    if (tid < TOK_PB) {
        int token = tok0 + tid;
        const float* zr = s_z + tid * RF_ZROW;
        float Z32 = xla_rowsum_sq_192(zr);

        int cnt = g_ccnt[token];
        float sBest = 3.4e38f;
        int iBest = 0x7fffffff;
        if (cnt <= MAXCAND) {
            for (int ci = 0; ci < cnt; ci++) {
                int k = g_cand[(size_t)token * MAXCAND + ci];
                float s = exact_score(zr, emb + (size_t)k * DIM, Z32, s_esq[k]);
                if (s < sBest || (s == sBest && k < iBest)) { sBest = s; iBest = k; }
            }
        } else {
            for (int k = 0; k < KCODES; k++) {
                float s = exact_score(zr, emb + (size_t)k * DIM, Z32, s_esq[k]);
                if (s < sBest || (s == sBest && k < iBest)) { sBest = s; iBest = k; }
            }
        }
        s_besti[tid] = iBest;
    }
    __syncthreads();

    float lsum = 0.f;
    const int NF4 = TOK_PB * (DIM / 4);
    for (int i = tid; i < NF4; i += 256) {
        int t  = i / (DIM / 4);
        int d4 = i % (DIM / 4);
        int token = tok0 + t;
        int idx = s_besti[t];
        float4 e = *(const float4*)(emb + (size_t)idx * DIM + d4 * 4);
        const float* zp = s_z + t * RF_ZROW + d4 * 4;
        float dx = __fsub_rn(e.x, zp[0]);
        float dy = __fsub_rn(e.y, zp[1]);
        float dz = __fsub_rn(e.z, zp[2]);
        float dw = __fsub_rn(e.w, zp[3]);
        lsum += dx * dx + dy * dy + dz * dz + dw * dw;
        float4 o;
        o.x = __fadd_rn(zp[0], dx);
        o.y = __fadd_rn(zp[1], dy);
        o.z = __fadd_rn(zp[2], dz);
        o.w = __fadd_rn(zp[3], dw);
        *(float4*)(out + (size_t)token * DIM + d4 * 4) = o;
    }
    if (tid < TOK_PB)
        out[(size_t)N_TOK * DIM + tok0 + tid] = (float)s_besti[tid];

    s_red[tid] = lsum;
    __syncthreads();
    #pragma unroll
    for (int s = 128; s > 0; s >>= 1) {
        if (tid < s) s_red[tid] += s_red[tid + s];
        __syncthreads();
    }
    if (tid == 0) g_part[blockIdx.x] = s_red[0];
}

// ============================================================
// Kernel F: deterministic loss finalize
// ============================================================
__global__ void vq_finalize_kernel(float* __restrict__ out) {
    __shared__ float red[512];
    int tid = threadIdx.x;
    float s = 0.f;
    for (int i = tid; i < NBLOCKS; i += 512) s += g_part[i];
    red[tid] = s;
    __syncthreads();
    #pragma unroll
    for (int o = 256; o > 0; o >>= 1) {
        if (tid < o) red[tid] += red[tid + o];
        __syncthreads();
    }
    if (tid == 0) {
        float mean = red[0] / (float)((size_t)N_TOK * DIM);
        out[(size_t)N_TOK * DIM + N_TOK] = (1.0f + BETA) * mean;
    }
}

// ============================================================
extern "C" void kernel_launch(void* const* d_in, const int* in_sizes, int n_in,
                              void* d_out, int out_size) {
    const float* z   = (const float*)d_in[0];
    const float* emb = (const float*)d_in[1];
    float* out = (float*)d_out;

    cudaFuncSetAttribute(vq_fastpass_kernel,
                         cudaFuncAttributeMaxDynamicSharedMemorySize, FP_TOTAL);
    cudaFuncSetAttribute(vq_refine_kernel,
                         cudaFuncAttributeMaxDynamicSharedMemorySize, RF_TOTAL);

    vq_cvt_z_kernel<<<2048, 256>>>(z);      // idx 0
    vq_cvt_e_kernel<<<256, 256>>>(emb);     // idx 1
    vq_esq_kernel<<<2, 256>>>(emb);         // idx 2
    vq_fastpass_kernel<<<NBLOCKS, 256, FP_TOTAL>>>();          // idx 3 (ncu capture)
    vq_refine_kernel<<<NBLOCKS, 256, RF_TOTAL>>>(z, emb, out); // idx 4
    vq_finalize_kernel<<<1, 512>>>(out);    // idx 5
}

// round 14
// speedup vs baseline: 5.2814x; 1.0184x over previous
#include <cuda_runtime.h>
#include <cuda_bf16.h>
#include <cstdint>

// Problem constants
#define N_TOK   262144
#define DIM     384
#define KCODES  512
#define BETA    0.25f

#define TOK_PB  192                    // tokens per fastpass block
#define N_PAD   262272                 // 1366 * 192 (padded token space)
#define FP_NBLK (N_PAD / TOK_PB)       // 1366
#define RF_TOK  128
#define RF_NBLK (N_TOK / RF_TOK)       // 2048
#define CODES_PC 64
#define NCHUNK  (KCODES / CODES_PC)    // 8
#define TAU     0.06f
#define MAXCAND 16
#define ZROWB   784                    // padded bf16 smem row: 384*2 + 16 bytes
#define FP_THREADS 384

__device__ float g_esq[KCODES];
__device__ float g_part[RF_NBLK];
__device__ __nv_bfloat16 g_zbf[(size_t)N_PAD * DIM];    // rows >= N_TOK stay zero
__device__ __nv_bfloat16 g_ebf[(size_t)KCODES * DIM];
__device__ int g_ccnt[N_PAD];
__device__ unsigned short g_cand[(size_t)N_PAD * MAXCAND];

// ---------------- PTX helpers (base sm_103 ISA only) ----------------
__device__ __forceinline__ uint32_t smem_u32(const void* p) {
    uint32_t a;
    asm("{ .reg .u64 t; cvta.to.shared.u64 t, %1; cvt.u32.u64 %0, t; }" : "=r"(a) : "l"(p));
    return a;
}

#define LDSM_X4(r0, r1, r2, r3, a) \
    asm volatile("ldmatrix.sync.aligned.m8n8.x4.shared.b16 {%0,%1,%2,%3}, [%4];" \
                 : "=r"(r0), "=r"(r1), "=r"(r2), "=r"(r3) : "r"(a))

#define MMA16816(d, a0, a1, a2, a3, b0, b1) \
    asm volatile("mma.sync.aligned.m16n8k16.row.col.f32.bf16.bf16.f32 " \
                 "{%0,%1,%2,%3}, {%4,%5,%6,%7}, {%8,%9}, {%0,%1,%2,%3};" \
                 : "+f"((d)[0]), "+f"((d)[1]), "+f"((d)[2]), "+f"((d)[3]) \
                 : "r"(a0), "r"(a1), "r"(a2), "r"(a3), "r"(b0), "r"(b1))

#define CP_ASYNC16(dst, src) \
    asm volatile("cp.async.cg.shared.global [%0], [%1], 16;" \
                 :: "r"((uint32_t)(dst)), "l"(src) : "memory")
#define CP_COMMIT() asm volatile("cp.async.commit_group;" ::: "memory")
#define CP_WAIT0()  asm volatile("cp.async.wait_group 0;" ::: "memory")

// ============================================================
// Exact-semantics primitives (DO NOT CHANGE — verified R6..R13)
// ============================================================
__device__ float xla_rowsum_sq_192(const float* __restrict__ x) {
    float W[6];
    #pragma unroll
    for (int w = 0; w < 6; w++) {
        float P[32];
        #pragma unroll
        for (int t = 0; t < 32; t++) {
            int b = (w * 32 + t) * 2;
            float p0 = __fmul_rn(x[b], x[b]);
            float p1 = __fmul_rn(x[b + 1], x[b + 1]);
            P[t] = __fadd_rn(p0, p1);
        }
        #pragma unroll
        for (int off = 16; off >= 1; off >>= 1) {
            #pragma unroll
            for (int t = 0; t < 16; t++)
                if (t < off) P[t] = __fadd_rn(P[t], P[t + off]);
        }
        W[w] = P[0];
    }
    float l0 = __fadd_rn(__fadd_rn(W[0], W[4]), W[2]);
    float l1 = __fadd_rn(__fadd_rn(W[1], W[5]), W[3]);
    return __fadd_rn(l0, l1);
}

__device__ __forceinline__ float exact_score(const float* __restrict__ zr,
                                             const float* __restrict__ er,
                                             float Z32, float esq32) {
    float acc = 0.f;
    const float4* er4 = (const float4*)er;
    #pragma unroll 4
    for (int d4 = 0; d4 < DIM / 4; d4++) {
        float4 e = er4[d4];
        acc = __fmaf_rn(zr[4 * d4 + 0], e.x, acc);
        acc = __fmaf_rn(zr[4 * d4 + 1], e.y, acc);
        acc = __fmaf_rn(zr[4 * d4 + 2], e.z, acc);
        acc = __fmaf_rn(zr[4 * d4 + 3], e.w, acc);
    }
    float v1 = __fadd_rn(Z32, __fmul_rn(-2.f, acc));
    return __fadd_rn(v1, esq32);
}

// ============================================================
// Kernel A: z fp32 -> bf16 + candidate-count reset (incl. padding)
// ============================================================
__global__ void vq_cvt_z_kernel(const float* __restrict__ z) {
    size_t i = (size_t)blockIdx.x * blockDim.x + threadIdx.x;
    size_t stride = (size_t)gridDim.x * blockDim.x;
    const size_t nz = (size_t)N_TOK * DIM / 2;
    for (size_t p = i; p < nz; p += stride) {
        float2 v = ((const float2*)z)[p];
        ((__nv_bfloat162*)g_zbf)[p] = __float22bfloat162_rn(v);
    }
    for (size_t p = i; p < N_PAD; p += stride) g_ccnt[p] = 0;
}

// ============================================================
// Kernel B: emb fp32 -> bf16
// ============================================================
__global__ void vq_cvt_e_kernel(const float* __restrict__ emb) {
    size_t i = (size_t)blockIdx.x * blockDim.x + threadIdx.x;
    size_t stride = (size_t)gridDim.x * blockDim.x;
    const size_t ne = (size_t)KCODES * DIM / 2;
    for (size_t p = i; p < ne; p += stride) {
        float2 v = ((const float2*)emb)[p];
        ((__nv_bfloat162*)g_ebf)[p] = __float22bfloat162_rn(v);
    }
}

// ============================================================
// Kernel C: e_sq[k] (verified)
// ============================================================
__global__ void vq_esq_kernel(const float* __restrict__ emb) {
    int k = blockIdx.x * blockDim.x + threadIdx.x;
    if (k < KCODES)
        g_esq[k] = xla_rowsum_sq_192(emb + (size_t)k * DIM);
}

// ============================================================
// Kernel D (launch idx 3 -> ncu capture): fast pass
// 12 warps, 192 tokens/block, single emb buffer; next-chunk load
// overlaps the candidate epilogue.
// ============================================================
#define FP_ESQ   0                        // 2048
#define FP_Z     2048                     // 192*784 = 150528
#define FP_E     152576                   // 64*784  = 50176
#define FP_TOTAL 202752

__global__ __launch_bounds__(FP_THREADS, 1)
void vq_fastpass_kernel() {
    extern __shared__ char smem[];
    const uint32_t smb = smem_u32(smem);
    const int tid = threadIdx.x;
    const int w   = tid >> 5;          // 0..11: token group
    const int lane = tid & 31;
    const int tok0 = blockIdx.x * TOK_PB;

    float* s_esq = (float*)(smem + FP_ESQ);
    for (int i = tid; i < KCODES; i += FP_THREADS) s_esq[i] = g_esq[i];

    // z tile: 192 rows x 784B (async) + emb chunk 0 (async)
    #pragma unroll
    for (int it = 0; it < 24; it++) {
        int idx = tid + it * FP_THREADS;   // 0..9215
        int row = idx / 48, c = idx % 48;
        CP_ASYNC16(smb + FP_Z + row * ZROWB + c * 16,
                   g_zbf + (size_t)(tok0 + row) * DIM + c * 8);
    }
    #pragma unroll
    for (int it = 0; it < 8; it++) {
        int idx = tid + it * FP_THREADS;   // 0..3071
        int row = idx / 48, c = idx % 48;
        CP_ASYNC16(smb + FP_E + row * ZROWB + c * 16,
                   g_ebf + (size_t)row * DIM + c * 8);
    }
    CP_COMMIT();

    // ldmatrix lane addressing
    const int lr = lane & 7;
    const int g4 = lane >> 3;
    const uint32_t aAddr0 = smb + FP_Z
        + (uint32_t)((w * 16 + (g4 & 1) * 8 + lr) * ZROWB + ((g4 >> 1) * 8) * 2);
    const uint32_t bAddr0 = smb + FP_E
        + (uint32_t)(((g4 >> 1) * 8 + lr) * ZROWB + ((g4 & 1) * 8) * 2);

    const int g  = lane >> 2;
    const int cq = lane & 3;
    const int tokA = tok0 + w * 16 + g;
    const int tokB = tokA + 8;

    float bv0 = 3.4e38f, bv1 = 3.4e38f;

    for (int ch = 0; ch < NCHUNK; ch++) {
        CP_WAIT0();
        __syncthreads();     // emb chunk ch resident; prior epilogue done

        const int cc0 = ch * CODES_PC;

        float acc[8][4];
        #pragma unroll
        for (int nt = 0; nt < 8; nt++)
            #pragma unroll
            for (int v = 0; v < 4; v++) acc[nt][v] = 0.f;

        // software-pipelined k-loop (verified R12/R13)
        uint32_t afr[2][4], bfr[2][16];
        LDSM_X4(afr[0][0], afr[0][1], afr[0][2], afr[0][3], aAddr0);
        #pragma unroll
        for (int i = 0; i < 4; i++)
            LDSM_X4(bfr[0][4 * i], bfr[0][4 * i + 1],
                    bfr[0][4 * i + 2], bfr[0][4 * i + 3],
                    bAddr0 + i * (16 * ZROWB));

        #pragma unroll
        for (int ks = 0; ks < DIM / 16; ks++) {
            const int cur = ks & 1, nxt = cur ^ 1;
            if (ks + 1 < DIM / 16) {
                LDSM_X4(afr[nxt][0], afr[nxt][1], afr[nxt][2], afr[nxt][3],
                        aAddr0 + (ks + 1) * 32);
                #pragma unroll
                for (int i = 0; i < 4; i++)
                    LDSM_X4(bfr[nxt][4 * i], bfr[nxt][4 * i + 1],
                            bfr[nxt][4 * i + 2], bfr[nxt][4 * i + 3],
                            bAddr0 + i * (16 * ZROWB) + (ks + 1) * 32);
            }
            #pragma unroll
            for (int i = 0; i < 4; i++) {
                MMA16816(acc[2 * i],     afr[cur][0], afr[cur][1], afr[cur][2], afr[cur][3],
                         bfr[cur][4 * i], bfr[cur][4 * i + 1]);
                MMA16816(acc[2 * i + 1], afr[cur][0], afr[cur][1], afr[cur][2], afr[cur][3],
                         bfr[cur][4 * i + 2], bfr[cur][4 * i + 3]);
            }
        }

        // all warps done reading emb smem -> start next chunk's load now,
        // overlapping the candidate epilogue below
        __syncthreads();
        if (ch + 1 < NCHUNK) {
            const int cc1 = (ch + 1) * CODES_PC;
            #pragma unroll
            for (int it = 0; it < 8; it++) {
                int idx = tid + it * FP_THREADS;
                int row = idx / 48, c = idx % 48;
                CP_ASYNC16(smb + FP_E + row * ZROWB + c * 16,
                           g_ebf + (size_t)(cc1 + row) * DIM + c * 8);
            }
            CP_COMMIT();
        }

        // per-chunk min across this token's quad
        float m0 = 3.4e38f, m1 = 3.4e38f;
        #pragma unroll
        for (int nt = 0; nt < 8; nt++) {
            int colb = cc0 + nt * 8 + cq * 2;
            float s00 = __fmaf_rn(-2.f, acc[nt][0], s_esq[colb]);
            float s01 = __fmaf_rn(-2.f, acc[nt][1], s_esq[colb + 1]);
            float s10 = __fmaf_rn(-2.f, acc[nt][2], s_esq[colb]);
            float s11 = __fmaf_rn(-2.f, acc[nt][3], s_esq[colb + 1]);
            m0 = fminf(m0, fminf(s00, s01));
            m1 = fminf(m1, fminf(s10, s11));
        }
        m0 = fminf(m0, __shfl_xor_sync(0xffffffffu, m0, 1));
        m0 = fminf(m0, __shfl_xor_sync(0xffffffffu, m0, 2));
        m1 = fminf(m1, __shfl_xor_sync(0xffffffffu, m1, 1));
        m1 = fminf(m1, __shfl_xor_sync(0xffffffffu, m1, 2));
        bv0 = fminf(bv0, m0);
        bv1 = fminf(bv1, m1);
        const float lim0 = bv0 + TAU, lim1 = bv1 + TAU;

        // candidate collection vs running min (superset-safe)
        #pragma unroll
        for (int nt = 0; nt < 8; nt++) {
            int colb = cc0 + nt * 8 + cq * 2;
            #pragma unroll
            for (int v = 0; v < 4; v++) {
                int col = colb + (v & 1);
                float s = __fmaf_rn(-2.f, acc[nt][v], s_esq[col]);
                int tok = (v < 2) ? tokA : tokB;
                float lim = (v < 2) ? lim0 : lim1;
                if (s <= lim) {
                    int p = atomicAdd(&g_ccnt[tok], 1);
                    if (p < MAXCAND) g_cand[(size_t)tok * MAXCAND + p] = (unsigned short)col;
                }
            }
        }
        // next iteration's CP_WAIT0 + __syncthreads guards buffer overwrite
    }
}

// ============================================================
// Kernel E: refine + epilogue (verified semantics + cnt==1 shortcut)
// ============================================================
#define RF_ZROW  385
#define RF_Z     0                         // 128*385*4 = 197120
#define RF_ESQ   197120                    // 2048
#define RF_BESTI 199168                    // 512
#define RF_RED   199680                    // 1024
#define RF_TOTAL 200704

__global__ __launch_bounds__(256, 1)
void vq_refine_kernel(const float* __restrict__ z,
                      const float* __restrict__ emb,
                      float* __restrict__ out) {
    extern __shared__ char smem[];
    float* s_z = (float*)(smem + RF_Z);
    float* s_esq = (float*)(smem + RF_ESQ);
    int* s_besti = (int*)(smem + RF_BESTI);
    float* s_red = (float*)(smem + RF_RED);
    const int tid = threadIdx.x;
    const int tok0 = blockIdx.x * RF_TOK;

    for (int i = tid; i < KCODES; i += 256) s_esq[i] = g_esq[i];

    #pragma unroll
    for (int it = 0; it < 48; it++) {
        int idx = tid + it * 256;
        int row = idx / 96, c = idx % 96;
        float4 v = *(const float4*)(z + (size_t)(tok0 + row) * DIM + c * 4);
        float* dst = s_z + row * RF_ZROW + c * 4;
        dst[0] = v.x; dst[1] = v.y; dst[2] = v.z; dst[3] = v.w;
    }
    __syncthreads();

    if (tid < RF_TOK) {
        int token = tok0 + tid;
        int cnt = g_ccnt[token];
        int iBest;
        if (cnt == 1) {
            // singleton candidate set provably contains the argmin -> done
            iBest = g_cand[(size_t)token * MAXCAND];
        } else {
            const float* zr = s_z + tid * RF_ZROW;
            float Z32 = xla_rowsum_sq_192(zr);
            float sBest = 3.4e38f;
            iBest = 0x7fffffff;
            if (cnt <= MAXCAND) {
                for (int ci = 0; ci < cnt; ci++) {
                    int k = g_cand[(size_t)token * MAXCAND + ci];
                    float s = exact_score(zr, emb + (size_t)k * DIM, Z32, s_esq[k]);
                    if (s < sBest || (s == sBest && k < iBest)) { sBest = s; iBest = k; }
                }
            } else {
                for (int k = 0; k < KCODES; k++) {
                    float s = exact_score(zr, emb + (size_t)k * DIM, Z32, s_esq[k]);
                    if (s < sBest || (s == sBest && k < iBest)) { sBest = s; iBest = k; }
                }
            }
        }
        s_besti[tid] = iBest;
    }
    __syncthreads();

    float lsum = 0.f;
    const int NF4 = RF_TOK * (DIM / 4);
    for (int i = tid; i < NF4; i += 256) {
        int t  = i / (DIM / 4);
        int d4 = i % (DIM / 4);
        int token = tok0 + t;
        int idx = s_besti[t];
        float4 e = *(const float4*)(emb + (size_t)idx * DIM + d4 * 4);
        const float* zp = s_z + t * RF_ZROW + d4 * 4;
        float dx = __fsub_rn(e.x, zp[0]);
        float dy = __fsub_rn(e.y, zp[1]);
        float dz = __fsub_rn(e.z, zp[2]);
        float dw = __fsub_rn(e.w, zp[3]);
        lsum += dx * dx + dy * dy + dz * dz + dw * dw;
        float4 o;
        o.x = __fadd_rn(zp[0], dx);
        o.y = __fadd_rn(zp[1], dy);
        o.z = __fadd_rn(zp[2], dz);
        o.w = __fadd_rn(zp[3], dw);
        *(float4*)(out + (size_t)token * DIM + d4 * 4) = o;
    }
    if (tid < RF_TOK)
        out[(size_t)N_TOK * DIM + tok0 + tid] = (float)s_besti[tid];

    s_red[tid] = lsum;
    __syncthreads();
    #pragma unroll
    for (int s = 128; s > 0; s >>= 1) {
        if (tid < s) s_red[tid] += s_red[tid + s];
        __syncthreads();
    }
    if (tid == 0) g_part[blockIdx.x] = s_red[0];
}

// ============================================================
// Kernel F: deterministic loss finalize
// ============================================================
__global__ void vq_finalize_kernel(float* __restrict__ out) {
    __shared__ float red[512];
    int tid = threadIdx.x;
    float s = 0.f;
    for (int i = tid; i < RF_NBLK; i += 512) s += g_part[i];
    red[tid] = s;
    __syncthreads();
    #pragma unroll
    for (int o = 256; o > 0; o >>= 1) {
        if (tid < o) red[tid] += red[tid + o];
        __syncthreads();
    }
    if (tid == 0) {
        float mean = red[0] / (float)((size_t)N_TOK * DIM);
        out[(size_t)N_TOK * DIM + N_TOK] = (1.0f + BETA) * mean;
    }
}

// ============================================================
extern "C" void kernel_launch(void* const* d_in, const int* in_sizes, int n_in,
                              void* d_out, int out_size) {
    const float* z   = (const float*)d_in[0];
    const float* emb = (const float*)d_in[1];
    float* out = (float*)d_out;

    cudaFuncSetAttribute(vq_fastpass_kernel,
                         cudaFuncAttributeMaxDynamicSharedMemorySize, FP_TOTAL);
    cudaFuncSetAttribute(vq_refine_kernel,
                         cudaFuncAttributeMaxDynamicSharedMemorySize, RF_TOTAL);

    vq_cvt_z_kernel<<<2048, 256>>>(z);      // idx 0
    vq_cvt_e_kernel<<<256, 256>>>(emb);     // idx 1
    vq_esq_kernel<<<2, 256>>>(emb);         // idx 2
    vq_fastpass_kernel<<<FP_NBLK, FP_THREADS, FP_TOTAL>>>();   // idx 3 (ncu)
    vq_refine_kernel<<<RF_NBLK, 256, RF_TOTAL>>>(z, emb, out); // idx 4
    vq_finalize_kernel<<<1, 512>>>(out);    // idx 5
}

// round 15
// speedup vs baseline: 6.5093x; 1.2325x over previous
#include <cuda_runtime.h>
#include <cuda_bf16.h>
#include <cstdint>

// Problem constants
#define N_TOK   262144
#define DIM     384
#define KCODES  512
#define BETA    0.25f

#define TOK_PB  192                    // tokens per fastpass block
#define N_PAD   262272                 // 1366 * 192 (padded token space)
#define FP_NBLK (N_PAD / TOK_PB)       // 1366
#define RF_TOK  128
#define RF_NBLK (N_TOK / RF_TOK)       // 2048
#define CODES_PC 64
#define NCHUNK  (KCODES / CODES_PC)    // 8
#define TAU     0.06f
#define MAXCAND 16
#define ZROWB   784                    // padded bf16 smem row: 384*2 + 16 bytes
#define FP_THREADS 384

__device__ float g_esq[KCODES];
__device__ float g_part[RF_NBLK];
__device__ __nv_bfloat16 g_zbf[(size_t)N_PAD * DIM];    // rows >= N_TOK stay zero
__device__ __nv_bfloat16 g_ebf[(size_t)KCODES * DIM];
__device__ int g_ccnt[N_PAD];
__device__ unsigned short g_cand[(size_t)N_PAD * MAXCAND];

// ---------------- PTX helpers (base sm_103 ISA only) ----------------
__device__ __forceinline__ uint32_t smem_u32(const void* p) {
    uint32_t a;
    asm("{ .reg .u64 t; cvta.to.shared.u64 t, %1; cvt.u32.u64 %0, t; }" : "=r"(a) : "l"(p));
    return a;
}

#define LDSM_X4(r0, r1, r2, r3, a) \
    asm volatile("ldmatrix.sync.aligned.m8n8.x4.shared.b16 {%0,%1,%2,%3}, [%4];" \
                 : "=r"(r0), "=r"(r1), "=r"(r2), "=r"(r3) : "r"(a))

#define MMA16816(d, a0, a1, a2, a3, b0, b1) \
    asm volatile("mma.sync.aligned.m16n8k16.row.col.f32.bf16.bf16.f32 " \
                 "{%0,%1,%2,%3}, {%4,%5,%6,%7}, {%8,%9}, {%0,%1,%2,%3};" \
                 : "+f"((d)[0]), "+f"((d)[1]), "+f"((d)[2]), "+f"((d)[3]) \
                 : "r"(a0), "r"(a1), "r"(a2), "r"(a3), "r"(b0), "r"(b1))

#define CP_ASYNC16(dst, src) \
    asm volatile("cp.async.cg.shared.global [%0], [%1], 16;" \
                 :: "r"((uint32_t)(dst)), "l"(src) : "memory")
#define CP_COMMIT() asm volatile("cp.async.commit_group;" ::: "memory")
#define CP_WAIT0()  asm volatile("cp.async.wait_group 0;" ::: "memory")

// ============================================================
// Exact-semantics primitives (DO NOT CHANGE — verified R6..R14)
// ============================================================
__device__ float xla_rowsum_sq_192(const float* __restrict__ x) {
    float W[6];
    #pragma unroll
    for (int w = 0; w < 6; w++) {
        float P[32];
        #pragma unroll
        for (int t = 0; t < 32; t++) {
            int b = (w * 32 + t) * 2;
            float p0 = __fmul_rn(x[b], x[b]);
            float p1 = __fmul_rn(x[b + 1], x[b + 1]);
            P[t] = __fadd_rn(p0, p1);
        }
        #pragma unroll
        for (int off = 16; off >= 1; off >>= 1) {
            #pragma unroll
            for (int t = 0; t < 16; t++)
                if (t < off) P[t] = __fadd_rn(P[t], P[t + off]);
        }
        W[w] = P[0];
    }
    float l0 = __fadd_rn(__fadd_rn(W[0], W[4]), W[2]);
    float l1 = __fadd_rn(__fadd_rn(W[1], W[5]), W[3]);
    return __fadd_rn(l0, l1);
}

__device__ __forceinline__ float exact_score(const float* __restrict__ zr,
                                             const float* __restrict__ er,
                                             float Z32, float esq32) {
    float acc = 0.f;
    const float4* er4 = (const float4*)er;
    #pragma unroll 4
    for (int d4 = 0; d4 < DIM / 4; d4++) {
        float4 e = er4[d4];
        acc = __fmaf_rn(zr[4 * d4 + 0], e.x, acc);
        acc = __fmaf_rn(zr[4 * d4 + 1], e.y, acc);
        acc = __fmaf_rn(zr[4 * d4 + 2], e.z, acc);
        acc = __fmaf_rn(zr[4 * d4 + 3], e.w, acc);
    }
    float v1 = __fadd_rn(Z32, __fmul_rn(-2.f, acc));
    return __fadd_rn(v1, esq32);
}

// ============================================================
// Kernel A: z fp32 -> bf16 + candidate-count reset (incl. padding)
// ============================================================
__global__ void vq_cvt_z_kernel(const float* __restrict__ z) {
    size_t i = (size_t)blockIdx.x * blockDim.x + threadIdx.x;
    size_t stride = (size_t)gridDim.x * blockDim.x;
    const size_t nz = (size_t)N_TOK * DIM / 2;
    for (size_t p = i; p < nz; p += stride) {
        float2 v = ((const float2*)z)[p];
        ((__nv_bfloat162*)g_zbf)[p] = __float22bfloat162_rn(v);
    }
    for (size_t p = i; p < N_PAD; p += stride) g_ccnt[p] = 0;
}

// ============================================================
// Kernel B: emb fp32 -> bf16
// ============================================================
__global__ void vq_cvt_e_kernel(const float* __restrict__ emb) {
    size_t i = (size_t)blockIdx.x * blockDim.x + threadIdx.x;
    size_t stride = (size_t)gridDim.x * blockDim.x;
    const size_t ne = (size_t)KCODES * DIM / 2;
    for (size_t p = i; p < ne; p += stride) {
        float2 v = ((const float2*)emb)[p];
        ((__nv_bfloat162*)g_ebf)[p] = __float22bfloat162_rn(v);
    }
}

// ============================================================
// Kernel C: e_sq[k] (verified)
// ============================================================
__global__ void vq_esq_kernel(const float* __restrict__ emb) {
    int k = blockIdx.x * blockDim.x + threadIdx.x;
    if (k < KCODES)
        g_esq[k] = xla_rowsum_sq_192(emb + (size_t)k * DIM);
}

// ============================================================
// Kernel D (launch idx 3 -> ncu capture): fast pass — byte-identical to R14
// ============================================================
#define FP_ESQ   0                        // 2048
#define FP_Z     2048                     // 192*784 = 150528
#define FP_E     152576                   // 64*784  = 50176
#define FP_TOTAL 202752

__global__ __launch_bounds__(FP_THREADS, 1)
void vq_fastpass_kernel() {
    extern __shared__ char smem[];
    const uint32_t smb = smem_u32(smem);
    const int tid = threadIdx.x;
    const int w   = tid >> 5;
    const int lane = tid & 31;
    const int tok0 = blockIdx.x * TOK_PB;

    float* s_esq = (float*)(smem + FP_ESQ);
    for (int i = tid; i < KCODES; i += FP_THREADS) s_esq[i] = g_esq[i];

    #pragma unroll
    for (int it = 0; it < 24; it++) {
        int idx = tid + it * FP_THREADS;
        int row = idx / 48, c = idx % 48;
        CP_ASYNC16(smb + FP_Z + row * ZROWB + c * 16,
                   g_zbf + (size_t)(tok0 + row) * DIM + c * 8);
    }
    #pragma unroll
    for (int it = 0; it < 8; it++) {
        int idx = tid + it * FP_THREADS;
        int row = idx / 48, c = idx % 48;
        CP_ASYNC16(smb + FP_E + row * ZROWB + c * 16,
                   g_ebf + (size_t)row * DIM + c * 8);
    }
    CP_COMMIT();

    const int lr = lane & 7;
    const int g4 = lane >> 3;
    const uint32_t aAddr0 = smb + FP_Z
        + (uint32_t)((w * 16 + (g4 & 1) * 8 + lr) * ZROWB + ((g4 >> 1) * 8) * 2);
    const uint32_t bAddr0 = smb + FP_E
        + (uint32_t)(((g4 >> 1) * 8 + lr) * ZROWB + ((g4 & 1) * 8) * 2);

    const int g  = lane >> 2;
    const int cq = lane & 3;
    const int tokA = tok0 + w * 16 + g;
    const int tokB = tokA + 8;

    float bv0 = 3.4e38f, bv1 = 3.4e38f;

    for (int ch = 0; ch < NCHUNK; ch++) {
        CP_WAIT0();
        __syncthreads();

        const int cc0 = ch * CODES_PC;

        float acc[8][4];
        #pragma unroll
        for (int nt = 0; nt < 8; nt++)
            #pragma unroll
            for (int v = 0; v < 4; v++) acc[nt][v] = 0.f;

        uint32_t afr[2][4], bfr[2][16];
        LDSM_X4(afr[0][0], afr[0][1], afr[0][2], afr[0][3], aAddr0);
        #pragma unroll
        for (int i = 0; i < 4; i++)
            LDSM_X4(bfr[0][4 * i], bfr[0][4 * i + 1],
                    bfr[0][4 * i + 2], bfr[0][4 * i + 3],
                    bAddr0 + i * (16 * ZROWB));

        #pragma unroll
        for (int ks = 0; ks < DIM / 16; ks++) {
            const int cur = ks & 1, nxt = cur ^ 1;
            if (ks + 1 < DIM / 16) {
                LDSM_X4(afr[nxt][0], afr[nxt][1], afr[nxt][2], afr[nxt][3],
                        aAddr0 + (ks + 1) * 32);
                #pragma unroll
                for (int i = 0; i < 4; i++)
                    LDSM_X4(bfr[nxt][4 * i], bfr[nxt][4 * i + 1],
                            bfr[nxt][4 * i + 2], bfr[nxt][4 * i + 3],
                            bAddr0 + i * (16 * ZROWB) + (ks + 1) * 32);
            }
            #pragma unroll
            for (int i = 0; i < 4; i++) {
                MMA16816(acc[2 * i],     afr[cur][0], afr[cur][1], afr[cur][2], afr[cur][3],
                         bfr[cur][4 * i], bfr[cur][4 * i + 1]);
                MMA16816(acc[2 * i + 1], afr[cur][0], afr[cur][1], afr[cur][2], afr[cur][3],
                         bfr[cur][4 * i + 2], bfr[cur][4 * i + 3]);
            }
        }

        __syncthreads();
        if (ch + 1 < NCHUNK) {
            const int cc1 = (ch + 1) * CODES_PC;
            #pragma unroll
            for (int it = 0; it < 8; it++) {
                int idx = tid + it * FP_THREADS;
                int row = idx / 48, c = idx % 48;
                CP_ASYNC16(smb + FP_E + row * ZROWB + c * 16,
                           g_ebf + (size_t)(cc1 + row) * DIM + c * 8);
            }
            CP_COMMIT();
        }

        float m0 = 3.4e38f, m1 = 3.4e38f;
        #pragma unroll
        for (int nt = 0; nt < 8; nt++) {
            int colb = cc0 + nt * 8 + cq * 2;
            float s00 = __fmaf_rn(-2.f, acc[nt][0], s_esq[colb]);
            float s01 = __fmaf_rn(-2.f, acc[nt][1], s_esq[colb + 1]);
            float s10 = __fmaf_rn(-2.f, acc[nt][2], s_esq[colb]);
            float s11 = __fmaf_rn(-2.f, acc[nt][3], s_esq[colb + 1]);
            m0 = fminf(m0, fminf(s00, s01));
            m1 = fminf(m1, fminf(s10, s11));
        }
        m0 = fminf(m0, __shfl_xor_sync(0xffffffffu, m0, 1));
        m0 = fminf(m0, __shfl_xor_sync(0xffffffffu, m0, 2));
        m1 = fminf(m1, __shfl_xor_sync(0xffffffffu, m1, 1));
        m1 = fminf(m1, __shfl_xor_sync(0xffffffffu, m1, 2));
        bv0 = fminf(bv0, m0);
        bv1 = fminf(bv1, m1);
        const float lim0 = bv0 + TAU, lim1 = bv1 + TAU;

        #pragma unroll
        for (int nt = 0; nt < 8; nt++) {
            int colb = cc0 + nt * 8 + cq * 2;
            #pragma unroll
            for (int v = 0; v < 4; v++) {
                int col = colb + (v & 1);
                float s = __fmaf_rn(-2.f, acc[nt][v], s_esq[col]);
                int tok = (v < 2) ? tokA : tokB;
                float lim = (v < 2) ? lim0 : lim1;
                if (s <= lim) {
                    int p = atomicAdd(&g_ccnt[tok], 1);
                    if (p < MAXCAND) g_cand[(size_t)tok * MAXCAND + p] = (unsigned short)col;
                }
            }
        }
    }
}

// ============================================================
// Kernel E: refine + epilogue — candidate-parallel scoring.
// Winner = lexicographic min over (score_bits, k): identical to the
// verified sequential (s<best || s==best&&k<iBest) loop, order-free.
// ============================================================
#define RF_ZROW  385
#define RF_Z     0                         // 128*385*4 = 197120
#define RF_ESQ   197120                    // 2048 -> 199168
#define RF_ZV    199168                    // 128*4 = 512 -> 199680
#define RF_CNT   199680                    // 128*4 = 512 -> 200192
#define RF_B64   200192                    // 128*8 = 1024 -> 201216
#define RF_BESTI 201216                    // 512 -> 201728
#define RF_PAIRS 201728                    // 2048*4 = 8192 -> 209920
#define RF_RED   209920                    // 1024 -> 210944
#define RF_NPAIR 210944                    // 16 -> 210960
#define RF_TOTAL 210960

__global__ __launch_bounds__(256, 1)
void vq_refine_kernel(const float* __restrict__ z,
                      const float* __restrict__ emb,
                      float* __restrict__ out) {
    extern __shared__ char smem[];
    float* s_z = (float*)(smem + RF_Z);
    float* s_esq = (float*)(smem + RF_ESQ);
    float* s_Z = (float*)(smem + RF_ZV);
    int* s_cnt = (int*)(smem + RF_CNT);
    unsigned long long* s_b64 = (unsigned long long*)(smem + RF_B64);
    int* s_besti = (int*)(smem + RF_BESTI);
    uint32_t* s_pairs = (uint32_t*)(smem + RF_PAIRS);
    float* s_red = (float*)(smem + RF_RED);
    int* s_npair = (int*)(smem + RF_NPAIR);
    const int tid = threadIdx.x;
    const int tok0 = blockIdx.x * RF_TOK;

    if (tid == 0) *s_npair = 0;
    for (int i = tid; i < KCODES; i += 256) s_esq[i] = g_esq[i];

    // stage z tile coalesced
    #pragma unroll
    for (int it = 0; it < 48; it++) {
        int idx = tid + it * 256;
        int row = idx / 96, c = idx % 96;
        float4 v = *(const float4*)(z + (size_t)(tok0 + row) * DIM + c * 4);
        float* dst = s_z + row * RF_ZROW + c * 4;
        dst[0] = v.x; dst[1] = v.y; dst[2] = v.z; dst[3] = v.w;
    }
    __syncthreads();

    // phase 1: per-token Z + candidate pair list
    if (tid < RF_TOK) {
        int token = tok0 + tid;
        int cnt = g_ccnt[token];
        s_cnt[tid] = cnt;
        s_b64[tid] = 0xffffffffffffffffull;
        s_Z[tid] = xla_rowsum_sq_192(s_z + tid * RF_ZROW);
        if (cnt == 1) {
            s_besti[tid] = g_cand[(size_t)token * MAXCAND];
        } else if (cnt > 1 && cnt <= MAXCAND) {
            int base = atomicAdd(s_npair, cnt);
            for (int ci = 0; ci < cnt; ci++)
                s_pairs[base + ci] =
                    ((uint32_t)tid << 16) | g_cand[(size_t)token * MAXCAND + ci];
        }
    }
    __syncthreads();

    // phase 2: candidate-parallel scoring (256 threads across all pairs)
    const int np = *s_npair;
    for (int p = tid; p < np; p += 256) {
        uint32_t pr = s_pairs[p];
        int t = pr >> 16;
        int k = pr & 0xffff;
        float s = exact_score(s_z + t * RF_ZROW, emb + (size_t)k * DIM,
                              s_Z[t], s_esq[k]);
        unsigned long long key =
            ((unsigned long long)__float_as_uint(s) << 32) | (unsigned)k;
        atomicMin(&s_b64[t], key);
    }
    __syncthreads();

    // phase 3: commit winners (+ rare overflow fallback, old serial path)
    if (tid < RF_TOK) {
        int cnt = s_cnt[tid];
        if (cnt > 1 && cnt <= MAXCAND) {
            s_besti[tid] = (int)(s_b64[tid] & 0xffffu);
        } else if (cnt > MAXCAND) {
            int token = tok0 + tid;
            const float* zr = s_z + tid * RF_ZROW;
            float Z32 = s_Z[tid];
            float sBest = 3.4e38f;
            int iBest = 0x7fffffff;
            for (int k = 0; k < KCODES; k++) {
                float s = exact_score(zr, emb + (size_t)k * DIM, Z32, s_esq[k]);
                if (s < sBest || (s == sBest && k < iBest)) { sBest = s; iBest = k; }
            }
            s_besti[tid] = iBest;
            (void)token;
        }
    }
    __syncthreads();

    // epilogue: z_q_out = fl(z + fl(z_q - z)), idx, loss partial
    float lsum = 0.f;
    const int NF4 = RF_TOK * (DIM / 4);
    for (int i = tid; i < NF4; i += 256) {
        int t  = i / (DIM / 4);
        int d4 = i % (DIM / 4);
        int token = tok0 + t;
        int idx = s_besti[t];
        float4 e = *(const float4*)(emb + (size_t)idx * DIM + d4 * 4);
        const float* zp = s_z + t * RF_ZROW + d4 * 4;
        float dx = __fsub_rn(e.x, zp[0]);
        float dy = __fsub_rn(e.y, zp[1]);
        float dz = __fsub_rn(e.z, zp[2]);
        float dw = __fsub_rn(e.w, zp[3]);
        lsum += dx * dx + dy * dy + dz * dz + dw * dw;
        float4 o;
        o.x = __fadd_rn(zp[0], dx);
        o.y = __fadd_rn(zp[1], dy);
        o.z = __fadd_rn(zp[2], dz);
        o.w = __fadd_rn(zp[3], dw);
        *(float4*)(out + (size_t)token * DIM + d4 * 4) = o;
    }
    if (tid < RF_TOK)
        out[(size_t)N_TOK * DIM + tok0 + tid] = (float)s_besti[tid];

    s_red[tid] = lsum;
    __syncthreads();
    #pragma unroll
    for (int s = 128; s > 0; s >>= 1) {
        if (tid < s) s_red[tid] += s_red[tid + s];
        __syncthreads();
    }
    if (tid == 0) g_part[blockIdx.x] = s_red[0];
}

// ============================================================
// Kernel F: deterministic loss finalize
// ============================================================
__global__ void vq_finalize_kernel(float* __restrict__ out) {
    __shared__ float red[512];
    int tid = threadIdx.x;
    float s = 0.f;
    for (int i = tid; i < RF_NBLK; i += 512) s += g_part[i];
    red[tid] = s;
    __syncthreads();
    #pragma unroll
    for (int o = 256; o > 0; o >>= 1) {
        if (tid < o) red[tid] += red[tid + o];
        __syncthreads();
    }
    if (tid == 0) {
        float mean = red[0] / (float)((size_t)N_TOK * DIM);
        out[(size_t)N_TOK * DIM + N_TOK] = (1.0f + BETA) * mean;
    }
}

// ============================================================
extern "C" void kernel_launch(void* const* d_in, const int* in_sizes, int n_in,
                              void* d_out, int out_size) {
    const float* z   = (const float*)d_in[0];
    const float* emb = (const float*)d_in[1];
    float* out = (float*)d_out;

    cudaFuncSetAttribute(vq_fastpass_kernel,
                         cudaFuncAttributeMaxDynamicSharedMemorySize, FP_TOTAL);
    cudaFuncSetAttribute(vq_refine_kernel,
                         cudaFuncAttributeMaxDynamicSharedMemorySize, RF_TOTAL);

    vq_cvt_z_kernel<<<2048, 256>>>(z);      // idx 0
    vq_cvt_e_kernel<<<256, 256>>>(emb);     // idx 1
    vq_esq_kernel<<<2, 256>>>(emb);         // idx 2
    vq_fastpass_kernel<<<FP_NBLK, FP_THREADS, FP_TOTAL>>>();   // idx 3 (ncu)
    vq_refine_kernel<<<RF_NBLK, 256, RF_TOTAL>>>(z, emb, out); // idx 4
    vq_finalize_kernel<<<1, 512>>>(out);    // idx 5
}

// round 16
// speedup vs baseline: 7.4986x; 1.1520x over previous
#include <cuda_runtime.h>
#include <cuda_bf16.h>
#include <cstdint>

// Problem constants
#define N_TOK   262144
#define DIM     384
#define KCODES  512
#define BETA    0.25f

#define TOK_PB  192                    // tokens per fastpass block
#define N_PAD   262272                 // 1366 * 192
#define FP_NBLK (N_PAD / TOK_PB)       // 1366
#define RF_TOK  64
#define RF_NBLK (N_TOK / RF_TOK)       // 4096
#define CODES_PC 64
#define NCHUNK  (KCODES / CODES_PC)    // 8
#define TAU     0.06f
#define MAXCAND 16
#define ZROWB   784                    // padded bf16 smem row
#define FP_THREADS 384

__device__ float g_esq[KCODES];
__device__ float g_part[RF_NBLK];
__device__ __nv_bfloat16 g_ebf[(size_t)KCODES * DIM];
__device__ int g_ccnt[N_PAD];
__device__ unsigned short g_cand[(size_t)N_PAD * MAXCAND];

// ---------------- PTX helpers (base sm_103 ISA only) ----------------
__device__ __forceinline__ uint32_t smem_u32(const void* p) {
    uint32_t a;
    asm("{ .reg .u64 t; cvta.to.shared.u64 t, %1; cvt.u32.u64 %0, t; }" : "=r"(a) : "l"(p));
    return a;
}

#define LDSM_X4(r0, r1, r2, r3, a) \
    asm volatile("ldmatrix.sync.aligned.m8n8.x4.shared.b16 {%0,%1,%2,%3}, [%4];" \
                 : "=r"(r0), "=r"(r1), "=r"(r2), "=r"(r3) : "r"(a))

#define MMA16816(d, a0, a1, a2, a3, b0, b1) \
    asm volatile("mma.sync.aligned.m16n8k16.row.col.f32.bf16.bf16.f32 " \
                 "{%0,%1,%2,%3}, {%4,%5,%6,%7}, {%8,%9}, {%0,%1,%2,%3};" \
                 : "+f"((d)[0]), "+f"((d)[1]), "+f"((d)[2]), "+f"((d)[3]) \
                 : "r"(a0), "r"(a1), "r"(a2), "r"(a3), "r"(b0), "r"(b1))

#define CP_ASYNC16(dst, src) \
    asm volatile("cp.async.cg.shared.global [%0], [%1], 16;" \
                 :: "r"((uint32_t)(dst)), "l"(src) : "memory")
#define CP_COMMIT() asm volatile("cp.async.commit_group;" ::: "memory")
#define CP_WAIT0()  asm volatile("cp.async.wait_group 0;" ::: "memory")

// ============================================================
// Exact-semantics primitives (DO NOT CHANGE — verified R6..R15)
// ============================================================
__device__ float xla_rowsum_sq_192(const float* __restrict__ x) {
    float W[6];
    #pragma unroll
    for (int w = 0; w < 6; w++) {
        float P[32];
        #pragma unroll
        for (int t = 0; t < 32; t++) {
            int b = (w * 32 + t) * 2;
            float p0 = __fmul_rn(x[b], x[b]);
            float p1 = __fmul_rn(x[b + 1], x[b + 1]);
            P[t] = __fadd_rn(p0, p1);
        }
        #pragma unroll
        for (int off = 16; off >= 1; off >>= 1) {
            #pragma unroll
            for (int t = 0; t < 16; t++)
                if (t < off) P[t] = __fadd_rn(P[t], P[t + off]);
        }
        W[w] = P[0];
    }
    float l0 = __fadd_rn(__fadd_rn(W[0], W[4]), W[2]);
    float l1 = __fadd_rn(__fadd_rn(W[1], W[5]), W[3]);
    return __fadd_rn(l0, l1);
}

__device__ __forceinline__ float exact_score(const float* __restrict__ zr,
                                             const float* __restrict__ er,
                                             float Z32, float esq32) {
    float acc = 0.f;
    const float4* er4 = (const float4*)er;
    #pragma unroll 4
    for (int d4 = 0; d4 < DIM / 4; d4++) {
        float4 e = er4[d4];
        acc = __fmaf_rn(zr[4 * d4 + 0], e.x, acc);
        acc = __fmaf_rn(zr[4 * d4 + 1], e.y, acc);
        acc = __fmaf_rn(zr[4 * d4 + 2], e.z, acc);
        acc = __fmaf_rn(zr[4 * d4 + 3], e.w, acc);
    }
    float v1 = __fadd_rn(Z32, __fmul_rn(-2.f, acc));
    return __fadd_rn(v1, esq32);
}

// ============================================================
// Kernel A: emb fp32 -> bf16 + candidate-count reset
// ============================================================
__global__ void vq_cvt_e_kernel(const float* __restrict__ emb) {
    size_t i = (size_t)blockIdx.x * blockDim.x + threadIdx.x;
    size_t stride = (size_t)gridDim.x * blockDim.x;
    const size_t ne = (size_t)KCODES * DIM / 2;
    for (size_t p = i; p < ne; p += stride) {
        float2 v = ((const float2*)emb)[p];
        ((__nv_bfloat162*)g_ebf)[p] = __float22bfloat162_rn(v);
    }
    for (size_t p = i; p < N_PAD; p += stride) g_ccnt[p] = 0;
}

// ============================================================
// Kernel B: e_sq[k] (verified)
// ============================================================
__global__ void vq_esq_kernel(const float* __restrict__ emb) {
    int k = blockIdx.x * blockDim.x + threadIdx.x;
    if (k < KCODES)
        g_esq[k] = xla_rowsum_sq_192(emb + (size_t)k * DIM);
}

// ============================================================
// Kernel C: fast pass — R14/R15 verified MMA core; z staged with
// inline fp32->bf16 conversion (identical __float22bfloat162_rn).
// ============================================================
#define FP_ESQ   0                        // 2048
#define FP_Z     2048                     // 192*784 = 150528
#define FP_E     152576                   // 64*784  = 50176
#define FP_TOTAL 202752

__global__ __launch_bounds__(FP_THREADS, 1)
void vq_fastpass_kernel(const float* __restrict__ z) {
    extern __shared__ char smem[];
    const uint32_t smb = smem_u32(smem);
    const int tid = threadIdx.x;
    const int w   = tid >> 5;
    const int lane = tid & 31;
    const int tok0 = blockIdx.x * TOK_PB;

    float* s_esq = (float*)(smem + FP_ESQ);
    for (int i = tid; i < KCODES; i += FP_THREADS) s_esq[i] = g_esq[i];

    // emb chunk 0 (async) first so it overlaps the z convert below
    #pragma unroll
    for (int it = 0; it < 8; it++) {
        int idx = tid + it * FP_THREADS;
        int row = idx / 48, c = idx % 48;
        CP_ASYNC16(smb + FP_E + row * ZROWB + c * 16,
                   g_ebf + (size_t)row * DIM + c * 8);
    }
    CP_COMMIT();

    // z tile: 192 rows, inline fp32 -> bf16 (rows >= N_TOK clamp; their
    // candidates land in padded g_ccnt slots that refine never reads)
    #pragma unroll
    for (int it = 0; it < 24; it++) {
        int idx = tid + it * FP_THREADS;    // 0..9215, unit = 8 floats
        int row = idx / 48, c = idx % 48;
        int zr = tok0 + row;
        if (zr >= N_TOK) zr = N_TOK - 1;
        const float* src = z + (size_t)zr * DIM + c * 8;
        float4 v0 = *(const float4*)(src);
        float4 v1 = *(const float4*)(src + 4);
        __nv_bfloat162 b0 = __float22bfloat162_rn(make_float2(v0.x, v0.y));
        __nv_bfloat162 b1 = __float22bfloat162_rn(make_float2(v0.z, v0.w));
        __nv_bfloat162 b2 = __float22bfloat162_rn(make_float2(v1.x, v1.y));
        __nv_bfloat162 b3 = __float22bfloat162_rn(make_float2(v1.z, v1.w));
        uint4 pk;
        pk.x = *(uint32_t*)&b0; pk.y = *(uint32_t*)&b1;
        pk.z = *(uint32_t*)&b2; pk.w = *(uint32_t*)&b3;
        *(uint4*)(smem + FP_Z + row * ZROWB + c * 16) = pk;
    }

    const int lr = lane & 7;
    const int g4 = lane >> 3;
    const uint32_t aAddr0 = smb + FP_Z
        + (uint32_t)((w * 16 + (g4 & 1) * 8 + lr) * ZROWB + ((g4 >> 1) * 8) * 2);
    const uint32_t bAddr0 = smb + FP_E
        + (uint32_t)(((g4 >> 1) * 8 + lr) * ZROWB + ((g4 & 1) * 8) * 2);

    const int g  = lane >> 2;
    const int cq = lane & 3;
    const int tokA = tok0 + w * 16 + g;
    const int tokB = tokA + 8;

    float bv0 = 3.4e38f, bv1 = 3.4e38f;

    for (int ch = 0; ch < NCHUNK; ch++) {
        CP_WAIT0();
        __syncthreads();

        const int cc0 = ch * CODES_PC;

        float acc[8][4];
        #pragma unroll
        for (int nt = 0; nt < 8; nt++)
            #pragma unroll
            for (int v = 0; v < 4; v++) acc[nt][v] = 0.f;

        uint32_t afr[2][4], bfr[2][16];
        LDSM_X4(afr[0][0], afr[0][1], afr[0][2], afr[0][3], aAddr0);
        #pragma unroll
        for (int i = 0; i < 4; i++)
            LDSM_X4(bfr[0][4 * i], bfr[0][4 * i + 1],
                    bfr[0][4 * i + 2], bfr[0][4 * i + 3],
                    bAddr0 + i * (16 * ZROWB));

        #pragma unroll
        for (int ks = 0; ks < DIM / 16; ks++) {
            const int cur = ks & 1, nxt = cur ^ 1;
            if (ks + 1 < DIM / 16) {
                LDSM_X4(afr[nxt][0], afr[nxt][1], afr[nxt][2], afr[nxt][3],
                        aAddr0 + (ks + 1) * 32);
                #pragma unroll
                for (int i = 0; i < 4; i++)
                    LDSM_X4(bfr[nxt][4 * i], bfr[nxt][4 * i + 1],
                            bfr[nxt][4 * i + 2], bfr[nxt][4 * i + 3],
                            bAddr0 + i * (16 * ZROWB) + (ks + 1) * 32);
            }
            #pragma unroll
            for (int i = 0; i < 4; i++) {
                MMA16816(acc[2 * i],     afr[cur][0], afr[cur][1], afr[cur][2], afr[cur][3],
                         bfr[cur][4 * i], bfr[cur][4 * i + 1]);
                MMA16816(acc[2 * i + 1], afr[cur][0], afr[cur][1], afr[cur][2], afr[cur][3],
                         bfr[cur][4 * i + 2], bfr[cur][4 * i + 3]);
            }
        }

        __syncthreads();
        if (ch + 1 < NCHUNK) {
            const int cc1 = (ch + 1) * CODES_PC;
            #pragma unroll
            for (int it = 0; it < 8; it++) {
                int idx = tid + it * FP_THREADS;
                int row = idx / 48, c = idx % 48;
                CP_ASYNC16(smb + FP_E + row * ZROWB + c * 16,
                           g_ebf + (size_t)(cc1 + row) * DIM + c * 8);
            }
            CP_COMMIT();
        }

        float m0 = 3.4e38f, m1 = 3.4e38f;
        #pragma unroll
        for (int nt = 0; nt < 8; nt++) {
            int colb = cc0 + nt * 8 + cq * 2;
            float s00 = __fmaf_rn(-2.f, acc[nt][0], s_esq[colb]);
            float s01 = __fmaf_rn(-2.f, acc[nt][1], s_esq[colb + 1]);
            float s10 = __fmaf_rn(-2.f, acc[nt][2], s_esq[colb]);
            float s11 = __fmaf_rn(-2.f, acc[nt][3], s_esq[colb + 1]);
            m0 = fminf(m0, fminf(s00, s01));
            m1 = fminf(m1, fminf(s10, s11));
        }
        m0 = fminf(m0, __shfl_xor_sync(0xffffffffu, m0, 1));
        m0 = fminf(m0, __shfl_xor_sync(0xffffffffu, m0, 2));
        m1 = fminf(m1, __shfl_xor_sync(0xffffffffu, m1, 1));
        m1 = fminf(m1, __shfl_xor_sync(0xffffffffu, m1, 2));
        bv0 = fminf(bv0, m0);
        bv1 = fminf(bv1, m1);
        const float lim0 = bv0 + TAU, lim1 = bv1 + TAU;

        #pragma unroll
        for (int nt = 0; nt < 8; nt++) {
            int colb = cc0 + nt * 8 + cq * 2;
            #pragma unroll
            for (int v = 0; v < 4; v++) {
                int col = colb + (v & 1);
                float s = __fmaf_rn(-2.f, acc[nt][v], s_esq[col]);
                int tok = (v < 2) ? tokA : tokB;
                float lim = (v < 2) ? lim0 : lim1;
                if (s <= lim) {
                    int p = atomicAdd(&g_ccnt[tok], 1);
                    if (p < MAXCAND) g_cand[(size_t)tok * MAXCAND + p] = (unsigned short)col;
                }
            }
        }
    }
}

// ============================================================
// Kernel D (launch idx 3 -> ncu capture): refine + epilogue.
// 64 tokens/block, 2 CTAs/SM. Candidate-parallel scoring (verified R15);
// winner = lexicographic min over (score_bits, k) — order-free.
// ============================================================
#define RF_ZROW  385
#define RF_Z     0                         // 64*385*4 = 98560
#define RF_ESQ   98560                     // 2048 -> 100608
#define RF_ZV    100608                    // 256 -> 100864
#define RF_CNT   100864                    // 256 -> 101120
#define RF_B64   101120                    // 512 -> 101632
#define RF_BESTI 101632                    // 256 -> 101888
#define RF_PAIRS 101888                    // 1024*4 -> 105984
#define RF_RED   105984                    // 1024 -> 107008
#define RF_NPAIR 107008                    // 16 -> 107024
#define RF_TOTAL 107024

__global__ __launch_bounds__(256, 2)
void vq_refine_kernel(const float* __restrict__ z,
                      const float* __restrict__ emb,
                      float* __restrict__ out) {
    extern __shared__ char smem[];
    float* s_z = (float*)(smem + RF_Z);
    float* s_esq = (float*)(smem + RF_ESQ);
    float* s_Z = (float*)(smem + RF_ZV);
    int* s_cnt = (int*)(smem + RF_CNT);
    unsigned long long* s_b64 = (unsigned long long*)(smem + RF_B64);
    int* s_besti = (int*)(smem + RF_BESTI);
    uint32_t* s_pairs = (uint32_t*)(smem + RF_PAIRS);
    float* s_red = (float*)(smem + RF_RED);
    int* s_npair = (int*)(smem + RF_NPAIR);
    const int tid = threadIdx.x;
    const int tok0 = blockIdx.x * RF_TOK;

    if (tid == 0) *s_npair = 0;
    for (int i = tid; i < KCODES; i += 256) s_esq[i] = g_esq[i];

    // stage z tile coalesced: 64 rows x 384 floats (padded rows of 385)
    #pragma unroll
    for (int it = 0; it < 24; it++) {
        int idx = tid + it * 256;          // 0..6143
        int row = idx / 96, c = idx % 96;
        float4 v = *(const float4*)(z + (size_t)(tok0 + row) * DIM + c * 4);
        float* dst = s_z + row * RF_ZROW + c * 4;
        dst[0] = v.x; dst[1] = v.y; dst[2] = v.z; dst[3] = v.w;
    }
    __syncthreads();

    // phase 1: per-token Z + candidate pair list
    if (tid < RF_TOK) {
        int token = tok0 + tid;
        int cnt = g_ccnt[token];
        s_cnt[tid] = cnt;
        s_b64[tid] = 0xffffffffffffffffull;
        s_Z[tid] = xla_rowsum_sq_192(s_z + tid * RF_ZROW);
        if (cnt == 1) {
            s_besti[tid] = g_cand[(size_t)token * MAXCAND];
        } else if (cnt > 1 && cnt <= MAXCAND) {
            int base = atomicAdd(s_npair, cnt);
            for (int ci = 0; ci < cnt; ci++)
                s_pairs[base + ci] =
                    ((uint32_t)tid << 16) | g_cand[(size_t)token * MAXCAND + ci];
        }
    }
    __syncthreads();

    // phase 2: candidate-parallel scoring
    const int np = *s_npair;
    for (int p = tid; p < np; p += 256) {
        uint32_t pr = s_pairs[p];
        int t = pr >> 16;
        int k = pr & 0xffff;
        float s = exact_score(s_z + t * RF_ZROW, emb + (size_t)k * DIM,
                              s_Z[t], s_esq[k]);
        unsigned long long key =
            ((unsigned long long)__float_as_uint(s) << 32) | (unsigned)k;
        atomicMin(&s_b64[t], key);
    }
    __syncthreads();

    // phase 3: commit winners (+ rare overflow fallback)
    if (tid < RF_TOK) {
        int cnt = s_cnt[tid];
        if (cnt > 1 && cnt <= MAXCAND) {
            s_besti[tid] = (int)(s_b64[tid] & 0xffffu);
        } else if (cnt > MAXCAND) {
            const float* zr = s_z + tid * RF_ZROW;
            float Z32 = s_Z[tid];
            float sBest = 3.4e38f;
            int iBest = 0x7fffffff;
            for (int k = 0; k < KCODES; k++) {
                float s = exact_score(zr, emb + (size_t)k * DIM, Z32, s_esq[k]);
                if (s < sBest || (s == sBest && k < iBest)) { sBest = s; iBest = k; }
            }
            s_besti[tid] = iBest;
        }
    }
    __syncthreads();

    // epilogue: z_q_out = fl(z + fl(z_q - z)), idx, loss partial
    float lsum = 0.f;
    const int NF4 = RF_TOK * (DIM / 4);    // 6144
    for (int i = tid; i < NF4; i += 256) {
        int t  = i / (DIM / 4);
        int d4 = i % (DIM / 4);
        int token = tok0 + t;
        int idx = s_besti[t];
        float4 e = *(const float4*)(emb + (size_t)idx * DIM + d4 * 4);
        const float* zp = s_z + t * RF_ZROW + d4 * 4;
        float dx = __fsub_rn(e.x, zp[0]);
        float dy = __fsub_rn(e.y, zp[1]);
        float dz = __fsub_rn(e.z, zp[2]);
        float dw = __fsub_rn(e.w, zp[3]);
        lsum += dx * dx + dy * dy + dz * dz + dw * dw;
        float4 o;
        o.x = __fadd_rn(zp[0], dx);
        o.y = __fadd_rn(zp[1], dy);
        o.z = __fadd_rn(zp[2], dz);
        o.w = __fadd_rn(zp[3], dw);
        *(float4*)(out + (size_t)token * DIM + d4 * 4) = o;
    }
    if (tid < RF_TOK)
        out[(size_t)N_TOK * DIM + tok0 + tid] = (float)s_besti[tid];

    s_red[tid] = lsum;
    __syncthreads();
    #pragma unroll
    for (int s = 128; s > 0; s >>= 1) {
        if (tid < s) s_red[tid] += s_red[tid + s];
        __syncthreads();
    }
    if (tid == 0) g_part[blockIdx.x] = s_red[0];
}

// ============================================================
// Kernel E: deterministic loss finalize
// ============================================================
__global__ void vq_finalize_kernel(float* __restrict__ out) {
    __shared__ float red[512];
    int tid = threadIdx.x;
    float s = 0.f;
    for (int i = tid; i < RF_NBLK; i += 512) s += g_part[i];
    red[tid] = s;
    __syncthreads();
    #pragma unroll
    for (int o = 256; o > 0; o >>= 1) {
        if (tid < o) red[tid] += red[tid + o];
        __syncthreads();
    }
    if (tid == 0) {
        float mean = red[0] / (float)((size_t)N_TOK * DIM);
        out[(size_t)N_TOK * DIM + N_TOK] = (1.0f + BETA) * mean;
    }
}

// ============================================================
extern "C" void kernel_launch(void* const* d_in, const int* in_sizes, int n_in,
                              void* d_out, int out_size) {
    const float* z   = (const float*)d_in[0];
    const float* emb = (const float*)d_in[1];
    float* out = (float*)d_out;

    cudaFuncSetAttribute(vq_fastpass_kernel,
                         cudaFuncAttributeMaxDynamicSharedMemorySize, FP_TOTAL);
    cudaFuncSetAttribute(vq_refine_kernel,
                         cudaFuncAttributeMaxDynamicSharedMemorySize, RF_TOTAL);

    vq_cvt_e_kernel<<<256, 256>>>(emb);     // idx 0
    vq_esq_kernel<<<2, 256>>>(emb);         // idx 1
    vq_fastpass_kernel<<<FP_NBLK, FP_THREADS, FP_TOTAL>>>(z);  // idx 2
    vq_refine_kernel<<<RF_NBLK, 256, RF_TOTAL>>>(z, emb, out); // idx 3 (ncu)
    vq_finalize_kernel<<<1, 512>>>(out);    // idx 4
}